// round 5
// baseline (speedup 1.0000x reference)
#include <cuda_runtime.h>
#include <cuda_bf16.h>
#include <cstdint>

#define BB   8
#define TT   2048
#define CIN  1024
#define HD   128
#define BT   (BB*TT)          // 16384 rows

typedef unsigned int u32;

// ---------------------------------------------------------------------------
// Device scratch (static globals: allocation-guard safe). bf16 hi/lo splits.
// ---------------------------------------------------------------------------
__device__ __align__(256) __nv_bfloat16 gQh[(size_t)BT * HD];
__device__ __align__(256) __nv_bfloat16 gQl[(size_t)BT * HD];
__device__ __align__(256) __nv_bfloat16 gKh[(size_t)BT * HD];
__device__ __align__(256) __nv_bfloat16 gKl[(size_t)BT * HD];
__device__ __align__(256) __nv_bfloat16 gVh[(size_t)BT * HD];
__device__ __align__(256) __nv_bfloat16 gVl[(size_t)BT * HD];
__device__ __align__(256) __nv_bfloat16 gWh[3][HD * CIN];   // W^T hi [o][n][k]
__device__ __align__(256) __nv_bfloat16 gWl[3][HD * CIN];   // W^T lo

// ---------------------------------------------------------------------------
// Helpers
// ---------------------------------------------------------------------------
__device__ __forceinline__ u32 pack_bf16(float x, float y) {
    __nv_bfloat162 h = __floats2bfloat162_rn(x, y);
    return *reinterpret_cast<u32*>(&h);
}
__device__ __forceinline__ void split_pair(float x, float y, u32& hi, u32& lo) {
    float hx = __bfloat162float(__float2bfloat16(x));
    float hy = __bfloat162float(__float2bfloat16(y));
    hi = pack_bf16(hx, hy);
    lo = pack_bf16(x - hx, y - hy);
}
__device__ __forceinline__ void mma_bf16(float* d, const u32* a, u32 b0, u32 b1) {
    asm volatile(
        "mma.sync.aligned.m16n8k16.row.col.f32.bf16.bf16.f32 "
        "{%0,%1,%2,%3}, {%4,%5,%6,%7}, {%8,%9}, {%0,%1,%2,%3};"
        : "+f"(d[0]), "+f"(d[1]), "+f"(d[2]), "+f"(d[3])
        : "r"(a[0]), "r"(a[1]), "r"(a[2]), "r"(a[3]), "r"(b0), "r"(b1));
}
__device__ __forceinline__ u32 smem_u32(const void* p) {
    u32 a;
    asm("{ .reg .u64 t; cvta.to.shared.u64 t, %1; cvt.u32.u64 %0, t; }"
        : "=r"(a) : "l"(p));
    return a;
}
__device__ __forceinline__ void ldsm4(u32 a, u32& r0, u32& r1, u32& r2, u32& r3) {
    asm volatile("ldmatrix.sync.aligned.m8n8.x4.shared.b16 {%0,%1,%2,%3}, [%4];"
                 : "=r"(r0), "=r"(r1), "=r"(r2), "=r"(r3) : "r"(a));
}
__device__ __forceinline__ void ldsm4t(u32 a, u32& r0, u32& r1, u32& r2, u32& r3) {
    asm volatile("ldmatrix.sync.aligned.m8n8.x4.trans.shared.b16 {%0,%1,%2,%3}, [%4];"
                 : "=r"(r0), "=r"(r1), "=r"(r2), "=r"(r3) : "r"(a));
}
#define CP16(dst, src) \
    asm volatile("cp.async.cg.shared.global [%0], [%1], 16;" \
                 :: "r"(dst), "l"(src) : "memory")
#define CP_COMMIT() asm volatile("cp.async.commit_group;" ::: "memory")
#define CP_WAIT(n)  asm volatile("cp.async.wait_group %0;" :: "n"(n) : "memory")

// ---------------------------------------------------------------------------
// Kernel A: transpose + split weights via smem tile (coalesced both sides).
// ---------------------------------------------------------------------------
__global__ void convert_w(const float* __restrict__ Wq,
                          const float* __restrict__ Wk,
                          const float* __restrict__ Wv)
{
    __shared__ float tile[32][33];
    const int o  = blockIdx.z;
    const float* W = (o == 0) ? Wq : (o == 1 ? Wk : Wv);
    const int n0 = blockIdx.x * 32;
    const int k0 = blockIdx.y * 32;
    const int tx = threadIdx.x, ty = threadIdx.y;

    #pragma unroll
    for (int i = ty; i < 32; i += 8)
        tile[i][tx] = W[(size_t)(k0 + i) * HD + n0 + tx];
    __syncthreads();
    #pragma unroll
    for (int i = ty; i < 32; i += 8) {
        float w  = tile[tx][i];                   // k = k0+tx, n = n0+i
        float hh = __bfloat162float(__float2bfloat16(w));
        gWh[o][(size_t)(n0 + i) * CIN + k0 + tx] = __float2bfloat16(hh);
        gWl[o][(size_t)(n0 + i) * CIN + k0 + tx] = __float2bfloat16(w - hh);
    }
}

// ---------------------------------------------------------------------------
// Kernel B: QKV GEMM. BM=128, BN=128, BK=32; 8 warps (4 wm x 2 wn).
// grid(3, 128): o fastest -> 3 CTAs with same m run together (X L2 reuse).
// ldmatrix fragments + register prefetch of next X/W tiles.
// ---------------------------------------------------------------------------
#define GS 40   // smem k-stride (halves): 80B rows, 16B aligned, LDSM-conflict-free
#define GEMM_SMEM (4 * 128 * GS * 2)

__global__ __launch_bounds__(256) void qkv_mma(const float* __restrict__ X)
{
    extern __shared__ __nv_bfloat16 smg[];
    __nv_bfloat16* Xh = smg;
    __nv_bfloat16* Xl = Xh + 128 * GS;
    __nv_bfloat16* Wh = Xl + 128 * GS;
    __nv_bfloat16* Wl = Wh + 128 * GS;
    const u32 Xh_b = smem_u32(Xh), Xl_b = smem_u32(Xl);
    const u32 Wh_b = smem_u32(Wh), Wl_b = smem_u32(Wl);

    const int t    = threadIdx.x;
    const int lane = t & 31;
    const int wrp  = t >> 5;
    const int wm   = wrp >> 1;
    const int wn   = wrp & 1;
    const int g    = lane >> 2;
    const int qd   = (lane & 3) << 1;
    const int j    = lane >> 3;
    const int lr   = lane & 7;
    const int o    = blockIdx.x;
    const size_t m0 = (size_t)blockIdx.y * 128;

    // ldmatrix byte offsets (stride 80B)
    u32 ga_off[2];
    #pragma unroll
    for (int mf = 0; mf < 2; mf++)
        ga_off[mf] = (wm * 32 + mf * 16 + ((j & 1) << 3) + lr) * 80 + ((j >> 1) << 4);
    const u32 gb_off = (wn * 64 + ((j >> 1) << 3) + lr) * 80 + ((j & 1) << 4);

    const __nv_bfloat16* Wgh = gWh[o];
    const __nv_bfloat16* Wgl = gWl[o];

    float acc[2][8][4];
    #pragma unroll
    for (int mf = 0; mf < 2; mf++)
        #pragma unroll
        for (int nf = 0; nf < 8; nf++)
            #pragma unroll
            for (int e = 0; e < 4; e++) acc[mf][nf][e] = 0.f;

    float4 xv[4];
    uint4  wvh[2], wvl[2];
    const int xr  = t >> 3;            // X row for loads
    const int xc  = (t & 7) << 2;      // X col (floats)
    const int wn_ = t >> 2;            // W row
    const int wc  = (t & 3) << 3;      // W col (halves)

    // prefetch iter 0
    #pragma unroll
    for (int i = 0; i < 4; i++)
        xv[i] = *reinterpret_cast<const float4*>(X + (m0 + xr + i * 32) * CIN + xc);
    #pragma unroll
    for (int i = 0; i < 2; i++) {
        wvh[i] = *reinterpret_cast<const uint4*>(&Wgh[(wn_ + i * 64) * CIN + wc]);
        wvl[i] = *reinterpret_cast<const uint4*>(&Wgl[(wn_ + i * 64) * CIN + wc]);
    }

    for (int it = 0; it < 32; it++) {
        __syncthreads();
        // store current tiles to smem (split X)
        #pragma unroll
        for (int i = 0; i < 4; i++) {
            u32 h0, l0, h1, l1;
            split_pair(xv[i].x, xv[i].y, h0, l0);
            split_pair(xv[i].z, xv[i].w, h1, l1);
            const int r = xr + i * 32;
            *reinterpret_cast<u32*>(&Xh[r * GS + xc])     = h0;
            *reinterpret_cast<u32*>(&Xh[r * GS + xc + 2]) = h1;
            *reinterpret_cast<u32*>(&Xl[r * GS + xc])     = l0;
            *reinterpret_cast<u32*>(&Xl[r * GS + xc + 2]) = l1;
        }
        #pragma unroll
        for (int i = 0; i < 2; i++) {
            *reinterpret_cast<uint4*>(&Wh[(wn_ + i * 64) * GS + wc]) = wvh[i];
            *reinterpret_cast<uint4*>(&Wl[(wn_ + i * 64) * GS + wc]) = wvl[i];
        }
        __syncthreads();

        if (it < 31) {
            const int k1 = (it + 1) * 32;
            #pragma unroll
            for (int i = 0; i < 4; i++)
                xv[i] = *reinterpret_cast<const float4*>(X + (m0 + xr + i * 32) * CIN + k1 + xc);
            #pragma unroll
            for (int i = 0; i < 2; i++) {
                wvh[i] = *reinterpret_cast<const uint4*>(&Wgh[(wn_ + i * 64) * CIN + k1 + wc]);
                wvl[i] = *reinterpret_cast<const uint4*>(&Wgl[(wn_ + i * 64) * CIN + k1 + wc]);
            }
        }

        #pragma unroll
        for (int ks = 0; ks < 2; ks++) {
            u32 ah[2][4], al[2][4];
            #pragma unroll
            for (int mf = 0; mf < 2; mf++) {
                ldsm4(Xh_b + ga_off[mf] + ks * 32, ah[mf][0], ah[mf][1], ah[mf][2], ah[mf][3]);
                ldsm4(Xl_b + ga_off[mf] + ks * 32, al[mf][0], al[mf][1], al[mf][2], al[mf][3]);
            }
            #pragma unroll
            for (int nf2 = 0; nf2 < 4; nf2++) {
                u32 bh0, bh1, bh2, bh3, bl0, bl1, bl2, bl3;
                ldsm4(Wh_b + gb_off + nf2 * (16 * 80) + ks * 32, bh0, bh1, bh2, bh3);
                ldsm4(Wl_b + gb_off + nf2 * (16 * 80) + ks * 32, bl0, bl1, bl2, bl3);
                #pragma unroll
                for (int mf = 0; mf < 2; mf++) {
                    mma_bf16(acc[mf][2 * nf2],     ah[mf], bh0, bh1);
                    mma_bf16(acc[mf][2 * nf2],     ah[mf], bl0, bl1);
                    mma_bf16(acc[mf][2 * nf2],     al[mf], bh0, bh1);
                    mma_bf16(acc[mf][2 * nf2 + 1], ah[mf], bh2, bh3);
                    mma_bf16(acc[mf][2 * nf2 + 1], ah[mf], bl2, bl3);
                    mma_bf16(acc[mf][2 * nf2 + 1], al[mf], bh2, bh3);
                }
            }
        }
    }

    // Epilogue: scale Q by 1/sqrt(1024), split to bf16 hi/lo globals
    const float scale = (o == 0) ? 0.03125f : 1.0f;
    __nv_bfloat16* Gh = (o == 0) ? gQh : (o == 1 ? gKh : gVh);
    __nv_bfloat16* Gl = (o == 0) ? gQl : (o == 1 ? gKl : gVl);
    #pragma unroll
    for (int mf = 0; mf < 2; mf++) {
        const size_t r = m0 + wm * 32 + mf * 16 + g;
        #pragma unroll
        for (int nf = 0; nf < 8; nf++) {
            const int col = wn * 64 + nf * 8 + qd;
            u32 hi, lo;
            split_pair(acc[mf][nf][0] * scale, acc[mf][nf][1] * scale, hi, lo);
            *reinterpret_cast<u32*>(&Gh[r * HD + col]) = hi;
            *reinterpret_cast<u32*>(&Gl[r * HD + col]) = lo;
            split_pair(acc[mf][nf][2] * scale, acc[mf][nf][3] * scale, hi, lo);
            *reinterpret_cast<u32*>(&Gh[(r + 8) * HD + col]) = hi;
            *reinterpret_cast<u32*>(&Gl[(r + 8) * HD + col]) = lo;
        }
    }
}

// ---------------------------------------------------------------------------
// Kernel C: causal flash attention.
// CTA: 64 q-rows, 4 warps. Q fragments held in registers for whole loop.
// K/V row-major in smem via cp.async (two commit groups -> V load overlaps S).
// K frags: ldmatrix.x4; V frags: ldmatrix.x4.trans (no explicit transpose).
// ---------------------------------------------------------------------------
#define AST 136                      // smem row stride in halves (272 B)
#define TILE_B (64 * AST * 2)        // one 64x128 bf16 tile: 17408 B
#define ATTN_SMEM (6 * TILE_B)       // Qh Ql Kh Kl Vh Vl = 104448 B

__device__ __forceinline__ void cp_tile64(u32 dst, const __nv_bfloat16* src, int t)
{
    #pragma unroll
    for (int i = 0; i < 8; i++) {
        const int c   = t + i * 128;
        const int row = c >> 4;
        const int col = c & 15;
        CP16(dst + row * 272 + col * 16, src + row * 128 + col * 8);
    }
}

__global__ __launch_bounds__(128) void attn_kernel(float* __restrict__ out)
{
    extern __shared__ __nv_bfloat16 sma[];
    const u32 base = smem_u32(sma);
    const u32 Qh_b = base,             Ql_b = base + TILE_B;
    const u32 Kh_b = base + 2*TILE_B,  Kl_b = base + 3*TILE_B;
    const u32 Vh_b = base + 4*TILE_B,  Vl_b = base + 5*TILE_B;

    const int t    = threadIdx.x;
    const int lane = t & 31;
    const int w    = t >> 5;
    const int g    = lane >> 2;
    const int qd   = (lane & 3) << 1;
    const int j    = lane >> 3;
    const int lr   = lane & 7;
    const int b    = blockIdx.y;
    const int qt   = (int)gridDim.x - 1 - (int)blockIdx.x;   // heavy first
    const int i0   = qt * 64;

    // ldmatrix byte offsets (stride 272B)
    const u32 a_off  = (w * 16 + ((j & 1) << 3) + lr) * 272 + ((j >> 1) << 4);
    const u32 kb_off = (((j >> 1) << 3) + lr) * 272 + ((j & 1) << 4);
    const u32 vb_off = (((j & 1) << 3) + lr) * 272 + ((j >> 1) << 4);

    // ---- Q tile -> smem (cp.async) -> register fragments ----
    {
        const __nv_bfloat16* Qgh = gQh + ((size_t)b * TT + i0) * HD;
        const __nv_bfloat16* Qgl = gQl + ((size_t)b * TT + i0) * HD;
        cp_tile64(Qh_b, Qgh, t);
        cp_tile64(Ql_b, Qgl, t);
        CP_COMMIT();
        CP_WAIT(0);
        __syncthreads();
    }
    u32 qh[8][4], ql[8][4];
    #pragma unroll
    for (int ks = 0; ks < 8; ks++) {
        ldsm4(Qh_b + a_off + ks * 32, qh[ks][0], qh[ks][1], qh[ks][2], qh[ks][3]);
        ldsm4(Ql_b + a_off + ks * 32, ql[ks][0], ql[ks][1], ql[ks][2], ql[ks][3]);
    }

    float O[16][4];
    #pragma unroll
    for (int nf = 0; nf < 16; nf++)
        #pragma unroll
        for (int e = 0; e < 4; e++) O[nf][e] = 0.f;
    float mrow[2] = {-1e30f, -1e30f};
    float lrow[2] = {0.f, 0.f};

    for (int jt = 0; jt <= qt; jt++) {
        __syncthreads();    // all warps done reading K/V of previous tile

        const __nv_bfloat16* Kgh = gKh + ((size_t)b * TT + jt * 64) * HD;
        const __nv_bfloat16* Kgl = gKl + ((size_t)b * TT + jt * 64) * HD;
        const __nv_bfloat16* Vgh = gVh + ((size_t)b * TT + jt * 64) * HD;
        const __nv_bfloat16* Vgl = gVl + ((size_t)b * TT + jt * 64) * HD;
        cp_tile64(Kh_b, Kgh, t);
        cp_tile64(Kl_b, Kgl, t);
        CP_COMMIT();
        cp_tile64(Vh_b, Vgh, t);
        cp_tile64(Vl_b, Vgl, t);
        CP_COMMIT();

        CP_WAIT(1);          // K arrived (V still in flight)
        __syncthreads();

        // ---- S = Q K^T (hi*hi + hi*lo + lo*hi) ----
        float s[8][4];
        #pragma unroll
        for (int nf = 0; nf < 8; nf++)
            #pragma unroll
            for (int e = 0; e < 4; e++) s[nf][e] = 0.f;

        #pragma unroll
        for (int ks = 0; ks < 8; ks++) {
            #pragma unroll
            for (int nf2 = 0; nf2 < 4; nf2++) {
                u32 bh0, bh1, bh2, bh3, bl0, bl1, bl2, bl3;
                ldsm4(Kh_b + kb_off + nf2 * (16 * 272) + ks * 32, bh0, bh1, bh2, bh3);
                ldsm4(Kl_b + kb_off + nf2 * (16 * 272) + ks * 32, bl0, bl1, bl2, bl3);
                mma_bf16(s[2 * nf2],     qh[ks], bh0, bh1);
                mma_bf16(s[2 * nf2],     qh[ks], bl0, bl1);
                mma_bf16(s[2 * nf2],     ql[ks], bh0, bh1);
                mma_bf16(s[2 * nf2 + 1], qh[ks], bh2, bh3);
                mma_bf16(s[2 * nf2 + 1], qh[ks], bl2, bl3);
                mma_bf16(s[2 * nf2 + 1], ql[ks], bh2, bh3);
            }
        }

        // ---- causal mask on diagonal tile ----
        if (jt == qt) {
            #pragma unroll
            for (int nf = 0; nf < 8; nf++) {
                const int c0 = nf * 8 + qd;
                const int r0 = w * 16 + g;
                if (c0     > r0)     s[nf][0] = -1e30f;
                if (c0 + 1 > r0)     s[nf][1] = -1e30f;
                if (c0     > r0 + 8) s[nf][2] = -1e30f;
                if (c0 + 1 > r0 + 8) s[nf][3] = -1e30f;
            }
        }

        // ---- online softmax ----
        float mx0 = -1e30f, mx1 = -1e30f;
        #pragma unroll
        for (int nf = 0; nf < 8; nf++) {
            mx0 = fmaxf(mx0, fmaxf(s[nf][0], s[nf][1]));
            mx1 = fmaxf(mx1, fmaxf(s[nf][2], s[nf][3]));
        }
        mx0 = fmaxf(mx0, __shfl_xor_sync(0xffffffffu, mx0, 1));
        mx0 = fmaxf(mx0, __shfl_xor_sync(0xffffffffu, mx0, 2));
        mx1 = fmaxf(mx1, __shfl_xor_sync(0xffffffffu, mx1, 1));
        mx1 = fmaxf(mx1, __shfl_xor_sync(0xffffffffu, mx1, 2));
        const float mn0 = fmaxf(mrow[0], mx0);
        const float mn1 = fmaxf(mrow[1], mx1);
        const float a0  = __expf(mrow[0] - mn0);
        const float a1  = __expf(mrow[1] - mn1);
        mrow[0] = mn0; mrow[1] = mn1;

        float sum0 = 0.f, sum1 = 0.f;
        #pragma unroll
        for (int nf = 0; nf < 8; nf++) {
            s[nf][0] = __expf(s[nf][0] - mn0);
            s[nf][1] = __expf(s[nf][1] - mn0);
            s[nf][2] = __expf(s[nf][2] - mn1);
            s[nf][3] = __expf(s[nf][3] - mn1);
            sum0 += s[nf][0] + s[nf][1];
            sum1 += s[nf][2] + s[nf][3];
        }
        sum0 += __shfl_xor_sync(0xffffffffu, sum0, 1);
        sum0 += __shfl_xor_sync(0xffffffffu, sum0, 2);
        sum1 += __shfl_xor_sync(0xffffffffu, sum1, 1);
        sum1 += __shfl_xor_sync(0xffffffffu, sum1, 2);
        lrow[0] = lrow[0] * a0 + sum0;
        lrow[1] = lrow[1] * a1 + sum1;

        #pragma unroll
        for (int nf = 0; nf < 16; nf++) {
            O[nf][0] *= a0; O[nf][1] *= a0;
            O[nf][2] *= a1; O[nf][3] *= a1;
        }

        CP_WAIT(0);          // V arrived
        __syncthreads();

        // ---- O += P V : V B-frags via ldmatrix.trans on row-major V ----
        #pragma unroll
        for (int ks = 0; ks < 4; ks++) {
            u32 ph[4], pl[4];
            split_pair(s[2 * ks][0],     s[2 * ks][1],     ph[0], pl[0]);
            split_pair(s[2 * ks][2],     s[2 * ks][3],     ph[1], pl[1]);
            split_pair(s[2 * ks + 1][0], s[2 * ks + 1][1], ph[2], pl[2]);
            split_pair(s[2 * ks + 1][2], s[2 * ks + 1][3], ph[3], pl[3]);
            #pragma unroll
            for (int nf2 = 0; nf2 < 8; nf2++) {
                u32 bh0, bh1, bh2, bh3, bl0, bl1, bl2, bl3;
                ldsm4t(Vh_b + vb_off + ks * (16 * 272) + nf2 * 32, bh0, bh1, bh2, bh3);
                ldsm4t(Vl_b + vb_off + ks * (16 * 272) + nf2 * 32, bl0, bl1, bl2, bl3);
                mma_bf16(O[2 * nf2],     ph, bh0, bh1);
                mma_bf16(O[2 * nf2],     ph, bl0, bl1);
                mma_bf16(O[2 * nf2],     pl, bh0, bh1);
                mma_bf16(O[2 * nf2 + 1], ph, bh2, bh3);
                mma_bf16(O[2 * nf2 + 1], ph, bl2, bl3);
                mma_bf16(O[2 * nf2 + 1], pl, bh2, bh3);
            }
        }
    }

    // ---- epilogue: normalize + store fp32 ----
    const float inv0 = 1.0f / lrow[0];
    const float inv1 = 1.0f / lrow[1];
    const size_t r0 = (size_t)b * TT + i0 + w * 16 + g;
    #pragma unroll
    for (int nf = 0; nf < 16; nf++) {
        const int col = nf * 8 + qd;
        float2 v0 = make_float2(O[nf][0] * inv0, O[nf][1] * inv0);
        float2 v1 = make_float2(O[nf][2] * inv1, O[nf][3] * inv1);
        *reinterpret_cast<float2*>(out + r0 * HD + col)       = v0;
        *reinterpret_cast<float2*>(out + (r0 + 8) * HD + col) = v1;
    }
}

// ---------------------------------------------------------------------------
extern "C" void kernel_launch(void* const* d_in, const int* in_sizes, int n_in,
                              void* d_out, int out_size)
{
    const float* X  = (const float*)d_in[0];   // [8,2048,1024]
    const float* Wq = (const float*)d_in[1];   // [1024,128]
    const float* Wk = (const float*)d_in[2];
    const float* Wv = (const float*)d_in[3];
    float* out = (float*)d_out;                // [8,2048,128]
    (void)in_sizes; (void)n_in; (void)out_size;

    cudaFuncSetAttribute(qkv_mma,
        cudaFuncAttributeMaxDynamicSharedMemorySize, GEMM_SMEM);
    cudaFuncSetAttribute(attn_kernel,
        cudaFuncAttributeMaxDynamicSharedMemorySize, ATTN_SMEM);

    convert_w<<<dim3(HD / 32, CIN / 32, 3), dim3(32, 8)>>>(Wq, Wk, Wv);
    qkv_mma<<<dim3(3, BT / 128), 256, GEMM_SMEM>>>(X);
    attn_kernel<<<dim3(TT / 64, BB), 128, ATTN_SMEM>>>(out);
}

// round 6
// speedup vs baseline: 1.0008x; 1.0008x over previous
#include <cuda_runtime.h>
#include <cuda_bf16.h>
#include <cstdint>

#define BB   8
#define TT   2048
#define CIN  1024
#define HD   128
#define BT   (BB*TT)          // 16384 rows

typedef unsigned int u32;

// ---------------------------------------------------------------------------
// Device scratch (static globals: allocation-guard safe). bf16 hi/lo splits.
// ---------------------------------------------------------------------------
__device__ __align__(256) __nv_bfloat16 gQh[(size_t)BT * HD];
__device__ __align__(256) __nv_bfloat16 gQl[(size_t)BT * HD];
__device__ __align__(256) __nv_bfloat16 gKh[(size_t)BT * HD];
__device__ __align__(256) __nv_bfloat16 gKl[(size_t)BT * HD];
__device__ __align__(256) __nv_bfloat16 gVh[(size_t)BT * HD];
__device__ __align__(256) __nv_bfloat16 gVl[(size_t)BT * HD];
__device__ __align__(256) __nv_bfloat16 gWh[3][HD * CIN];   // W^T hi [o][n][k]
__device__ __align__(256) __nv_bfloat16 gWl[3][HD * CIN];   // W^T lo

// ---------------------------------------------------------------------------
// Helpers
// ---------------------------------------------------------------------------
__device__ __forceinline__ u32 pack_bf16(float x, float y) {
    __nv_bfloat162 h = __floats2bfloat162_rn(x, y);
    return *reinterpret_cast<u32*>(&h);
}
__device__ __forceinline__ void split_pair(float x, float y, u32& hi, u32& lo) {
    float hx = __bfloat162float(__float2bfloat16(x));
    float hy = __bfloat162float(__float2bfloat16(y));
    hi = pack_bf16(hx, hy);
    lo = pack_bf16(x - hx, y - hy);
}
__device__ __forceinline__ void mma_bf16(float* d, const u32* a, u32 b0, u32 b1) {
    asm volatile(
        "mma.sync.aligned.m16n8k16.row.col.f32.bf16.bf16.f32 "
        "{%0,%1,%2,%3}, {%4,%5,%6,%7}, {%8,%9}, {%0,%1,%2,%3};"
        : "+f"(d[0]), "+f"(d[1]), "+f"(d[2]), "+f"(d[3])
        : "r"(a[0]), "r"(a[1]), "r"(a[2]), "r"(a[3]), "r"(b0), "r"(b1));
}
__device__ __forceinline__ u32 smem_u32(const void* p) {
    u32 a;
    asm("{ .reg .u64 t; cvta.to.shared.u64 t, %1; cvt.u32.u64 %0, t; }"
        : "=r"(a) : "l"(p));
    return a;
}
__device__ __forceinline__ void ldsm4(u32 a, u32& r0, u32& r1, u32& r2, u32& r3) {
    asm volatile("ldmatrix.sync.aligned.m8n8.x4.shared.b16 {%0,%1,%2,%3}, [%4];"
                 : "=r"(r0), "=r"(r1), "=r"(r2), "=r"(r3) : "r"(a));
}
__device__ __forceinline__ void ldsm4t(u32 a, u32& r0, u32& r1, u32& r2, u32& r3) {
    asm volatile("ldmatrix.sync.aligned.m8n8.x4.trans.shared.b16 {%0,%1,%2,%3}, [%4];"
                 : "=r"(r0), "=r"(r1), "=r"(r2), "=r"(r3) : "r"(a));
}
#define CP16(dst, src) \
    asm volatile("cp.async.cg.shared.global [%0], [%1], 16;" \
                 :: "r"(dst), "l"(src) : "memory")
#define CP_COMMIT() asm volatile("cp.async.commit_group;" ::: "memory")
#define CP_WAIT(n)  asm volatile("cp.async.wait_group %0;" :: "n"(n) : "memory")

// ---------------------------------------------------------------------------
// Kernel A: transpose + split weights via smem tile (coalesced both sides).
// ---------------------------------------------------------------------------
__global__ void convert_w(const float* __restrict__ Wq,
                          const float* __restrict__ Wk,
                          const float* __restrict__ Wv)
{
    __shared__ float tile[32][33];
    const int o  = blockIdx.z;
    const float* W = (o == 0) ? Wq : (o == 1 ? Wk : Wv);
    const int n0 = blockIdx.x * 32;
    const int k0 = blockIdx.y * 32;
    const int tx = threadIdx.x, ty = threadIdx.y;

    #pragma unroll
    for (int i = ty; i < 32; i += 8)
        tile[i][tx] = W[(size_t)(k0 + i) * HD + n0 + tx];
    __syncthreads();
    #pragma unroll
    for (int i = ty; i < 32; i += 8) {
        float w  = tile[tx][i];                   // k = k0+tx, n = n0+i
        float hh = __bfloat162float(__float2bfloat16(w));
        gWh[o][(size_t)(n0 + i) * CIN + k0 + tx] = __float2bfloat16(hh);
        gWl[o][(size_t)(n0 + i) * CIN + k0 + tx] = __float2bfloat16(w - hh);
    }
}

// ---------------------------------------------------------------------------
// Kernel B: QKV GEMM. BM=128, BN=128, BK=32; 8 warps (4 wm x 2 wn).
// grid(3, 128): o fastest -> 3 CTAs with same m run together (X L2 reuse).
// ldmatrix fragments + register prefetch of next X/W tiles.
// ---------------------------------------------------------------------------
#define GS 40   // smem k-stride (halves): 80B rows, 16B aligned, LDSM-conflict-free
#define GEMM_SMEM (4 * 128 * GS * 2)

__global__ __launch_bounds__(256) void qkv_mma(const float* __restrict__ X)
{
    extern __shared__ __nv_bfloat16 smg[];
    __nv_bfloat16* Xh = smg;
    __nv_bfloat16* Xl = Xh + 128 * GS;
    __nv_bfloat16* Wh = Xl + 128 * GS;
    __nv_bfloat16* Wl = Wh + 128 * GS;
    const u32 Xh_b = smem_u32(Xh), Xl_b = smem_u32(Xl);
    const u32 Wh_b = smem_u32(Wh), Wl_b = smem_u32(Wl);

    const int t    = threadIdx.x;
    const int lane = t & 31;
    const int wrp  = t >> 5;
    const int wm   = wrp >> 1;
    const int wn   = wrp & 1;
    const int g    = lane >> 2;
    const int qd   = (lane & 3) << 1;
    const int j    = lane >> 3;
    const int lr   = lane & 7;
    const int o    = blockIdx.x;
    const size_t m0 = (size_t)blockIdx.y * 128;

    // ldmatrix byte offsets (stride 80B)
    u32 ga_off[2];
    #pragma unroll
    for (int mf = 0; mf < 2; mf++)
        ga_off[mf] = (wm * 32 + mf * 16 + ((j & 1) << 3) + lr) * 80 + ((j >> 1) << 4);
    const u32 gb_off = (wn * 64 + ((j >> 1) << 3) + lr) * 80 + ((j & 1) << 4);

    const __nv_bfloat16* Wgh = gWh[o];
    const __nv_bfloat16* Wgl = gWl[o];

    float acc[2][8][4];
    #pragma unroll
    for (int mf = 0; mf < 2; mf++)
        #pragma unroll
        for (int nf = 0; nf < 8; nf++)
            #pragma unroll
            for (int e = 0; e < 4; e++) acc[mf][nf][e] = 0.f;

    float4 xv[4];
    uint4  wvh[2], wvl[2];
    const int xr  = t >> 3;            // X row for loads
    const int xc  = (t & 7) << 2;      // X col (floats)
    const int wn_ = t >> 2;            // W row
    const int wc  = (t & 3) << 3;      // W col (halves)

    // prefetch iter 0
    #pragma unroll
    for (int i = 0; i < 4; i++)
        xv[i] = *reinterpret_cast<const float4*>(X + (m0 + xr + i * 32) * CIN + xc);
    #pragma unroll
    for (int i = 0; i < 2; i++) {
        wvh[i] = *reinterpret_cast<const uint4*>(&Wgh[(wn_ + i * 64) * CIN + wc]);
        wvl[i] = *reinterpret_cast<const uint4*>(&Wgl[(wn_ + i * 64) * CIN + wc]);
    }

    for (int it = 0; it < 32; it++) {
        __syncthreads();
        // store current tiles to smem (split X)
        #pragma unroll
        for (int i = 0; i < 4; i++) {
            u32 h0, l0, h1, l1;
            split_pair(xv[i].x, xv[i].y, h0, l0);
            split_pair(xv[i].z, xv[i].w, h1, l1);
            const int r = xr + i * 32;
            *reinterpret_cast<u32*>(&Xh[r * GS + xc])     = h0;
            *reinterpret_cast<u32*>(&Xh[r * GS + xc + 2]) = h1;
            *reinterpret_cast<u32*>(&Xl[r * GS + xc])     = l0;
            *reinterpret_cast<u32*>(&Xl[r * GS + xc + 2]) = l1;
        }
        #pragma unroll
        for (int i = 0; i < 2; i++) {
            *reinterpret_cast<uint4*>(&Wh[(wn_ + i * 64) * GS + wc]) = wvh[i];
            *reinterpret_cast<uint4*>(&Wl[(wn_ + i * 64) * GS + wc]) = wvl[i];
        }
        __syncthreads();

        if (it < 31) {
            const int k1 = (it + 1) * 32;
            #pragma unroll
            for (int i = 0; i < 4; i++)
                xv[i] = *reinterpret_cast<const float4*>(X + (m0 + xr + i * 32) * CIN + k1 + xc);
            #pragma unroll
            for (int i = 0; i < 2; i++) {
                wvh[i] = *reinterpret_cast<const uint4*>(&Wgh[(wn_ + i * 64) * CIN + k1 + wc]);
                wvl[i] = *reinterpret_cast<const uint4*>(&Wgl[(wn_ + i * 64) * CIN + k1 + wc]);
            }
        }

        #pragma unroll
        for (int ks = 0; ks < 2; ks++) {
            u32 ah[2][4], al[2][4];
            #pragma unroll
            for (int mf = 0; mf < 2; mf++) {
                ldsm4(Xh_b + ga_off[mf] + ks * 32, ah[mf][0], ah[mf][1], ah[mf][2], ah[mf][3]);
                ldsm4(Xl_b + ga_off[mf] + ks * 32, al[mf][0], al[mf][1], al[mf][2], al[mf][3]);
            }
            #pragma unroll
            for (int nf2 = 0; nf2 < 4; nf2++) {
                u32 bh0, bh1, bh2, bh3, bl0, bl1, bl2, bl3;
                ldsm4(Wh_b + gb_off + nf2 * (16 * 80) + ks * 32, bh0, bh1, bh2, bh3);
                ldsm4(Wl_b + gb_off + nf2 * (16 * 80) + ks * 32, bl0, bl1, bl2, bl3);
                #pragma unroll
                for (int mf = 0; mf < 2; mf++) {
                    mma_bf16(acc[mf][2 * nf2],     ah[mf], bh0, bh1);
                    mma_bf16(acc[mf][2 * nf2],     ah[mf], bl0, bl1);
                    mma_bf16(acc[mf][2 * nf2],     al[mf], bh0, bh1);
                    mma_bf16(acc[mf][2 * nf2 + 1], ah[mf], bh2, bh3);
                    mma_bf16(acc[mf][2 * nf2 + 1], ah[mf], bl2, bl3);
                    mma_bf16(acc[mf][2 * nf2 + 1], al[mf], bh2, bh3);
                }
            }
        }
    }

    // Epilogue: scale Q by 1/sqrt(1024), split to bf16 hi/lo globals
    const float scale = (o == 0) ? 0.03125f : 1.0f;
    __nv_bfloat16* Gh = (o == 0) ? gQh : (o == 1 ? gKh : gVh);
    __nv_bfloat16* Gl = (o == 0) ? gQl : (o == 1 ? gKl : gVl);
    #pragma unroll
    for (int mf = 0; mf < 2; mf++) {
        const size_t r = m0 + wm * 32 + mf * 16 + g;
        #pragma unroll
        for (int nf = 0; nf < 8; nf++) {
            const int col = wn * 64 + nf * 8 + qd;
            u32 hi, lo;
            split_pair(acc[mf][nf][0] * scale, acc[mf][nf][1] * scale, hi, lo);
            *reinterpret_cast<u32*>(&Gh[r * HD + col]) = hi;
            *reinterpret_cast<u32*>(&Gl[r * HD + col]) = lo;
            split_pair(acc[mf][nf][2] * scale, acc[mf][nf][3] * scale, hi, lo);
            *reinterpret_cast<u32*>(&Gh[(r + 8) * HD + col]) = hi;
            *reinterpret_cast<u32*>(&Gl[(r + 8) * HD + col]) = lo;
        }
    }
}

// ---------------------------------------------------------------------------
// Kernel C: causal flash attention.
// CTA: 64 q-rows, 4 warps. Q fragments held in registers for whole loop.
// K/V row-major in smem via cp.async (two commit groups -> V load overlaps S).
// K frags: ldmatrix.x4; V frags: ldmatrix.x4.trans (no explicit transpose).
// ---------------------------------------------------------------------------
#define AST 136                      // smem row stride in halves (272 B)
#define TILE_B (64 * AST * 2)        // one 64x128 bf16 tile: 17408 B
#define ATTN_SMEM (6 * TILE_B)       // Qh Ql Kh Kl Vh Vl = 104448 B

__device__ __forceinline__ void cp_tile64(u32 dst, const __nv_bfloat16* src, int t)
{
    #pragma unroll
    for (int i = 0; i < 8; i++) {
        const int c   = t + i * 128;
        const int row = c >> 4;
        const int col = c & 15;
        CP16(dst + row * 272 + col * 16, src + row * 128 + col * 8);
    }
}

__global__ __launch_bounds__(128) void attn_kernel(float* __restrict__ out)
{
    extern __shared__ __nv_bfloat16 sma[];
    const u32 base = smem_u32(sma);
    const u32 Qh_b = base,             Ql_b = base + TILE_B;
    const u32 Kh_b = base + 2*TILE_B,  Kl_b = base + 3*TILE_B;
    const u32 Vh_b = base + 4*TILE_B,  Vl_b = base + 5*TILE_B;

    const int t    = threadIdx.x;
    const int lane = t & 31;
    const int w    = t >> 5;
    const int g    = lane >> 2;
    const int qd   = (lane & 3) << 1;
    const int j    = lane >> 3;
    const int lr   = lane & 7;
    const int b    = blockIdx.y;
    const int qt   = (int)gridDim.x - 1 - (int)blockIdx.x;   // heavy first
    const int i0   = qt * 64;

    // ldmatrix byte offsets (stride 272B)
    const u32 a_off  = (w * 16 + ((j & 1) << 3) + lr) * 272 + ((j >> 1) << 4);
    const u32 kb_off = (((j >> 1) << 3) + lr) * 272 + ((j & 1) << 4);
    const u32 vb_off = (((j & 1) << 3) + lr) * 272 + ((j >> 1) << 4);

    // ---- Q tile -> smem (cp.async) -> register fragments ----
    {
        const __nv_bfloat16* Qgh = gQh + ((size_t)b * TT + i0) * HD;
        const __nv_bfloat16* Qgl = gQl + ((size_t)b * TT + i0) * HD;
        cp_tile64(Qh_b, Qgh, t);
        cp_tile64(Ql_b, Qgl, t);
        CP_COMMIT();
        CP_WAIT(0);
        __syncthreads();
    }
    u32 qh[8][4], ql[8][4];
    #pragma unroll
    for (int ks = 0; ks < 8; ks++) {
        ldsm4(Qh_b + a_off + ks * 32, qh[ks][0], qh[ks][1], qh[ks][2], qh[ks][3]);
        ldsm4(Ql_b + a_off + ks * 32, ql[ks][0], ql[ks][1], ql[ks][2], ql[ks][3]);
    }

    float O[16][4];
    #pragma unroll
    for (int nf = 0; nf < 16; nf++)
        #pragma unroll
        for (int e = 0; e < 4; e++) O[nf][e] = 0.f;
    float mrow[2] = {-1e30f, -1e30f};
    float lrow[2] = {0.f, 0.f};

    for (int jt = 0; jt <= qt; jt++) {
        __syncthreads();    // all warps done reading K/V of previous tile

        const __nv_bfloat16* Kgh = gKh + ((size_t)b * TT + jt * 64) * HD;
        const __nv_bfloat16* Kgl = gKl + ((size_t)b * TT + jt * 64) * HD;
        const __nv_bfloat16* Vgh = gVh + ((size_t)b * TT + jt * 64) * HD;
        const __nv_bfloat16* Vgl = gVl + ((size_t)b * TT + jt * 64) * HD;
        cp_tile64(Kh_b, Kgh, t);
        cp_tile64(Kl_b, Kgl, t);
        CP_COMMIT();
        cp_tile64(Vh_b, Vgh, t);
        cp_tile64(Vl_b, Vgl, t);
        CP_COMMIT();

        CP_WAIT(1);          // K arrived (V still in flight)
        __syncthreads();

        // ---- S = Q K^T (hi*hi + hi*lo + lo*hi) ----
        float s[8][4];
        #pragma unroll
        for (int nf = 0; nf < 8; nf++)
            #pragma unroll
            for (int e = 0; e < 4; e++) s[nf][e] = 0.f;

        #pragma unroll
        for (int ks = 0; ks < 8; ks++) {
            #pragma unroll
            for (int nf2 = 0; nf2 < 4; nf2++) {
                u32 bh0, bh1, bh2, bh3, bl0, bl1, bl2, bl3;
                ldsm4(Kh_b + kb_off + nf2 * (16 * 272) + ks * 32, bh0, bh1, bh2, bh3);
                ldsm4(Kl_b + kb_off + nf2 * (16 * 272) + ks * 32, bl0, bl1, bl2, bl3);
                mma_bf16(s[2 * nf2],     qh[ks], bh0, bh1);
                mma_bf16(s[2 * nf2],     qh[ks], bl0, bl1);
                mma_bf16(s[2 * nf2],     ql[ks], bh0, bh1);
                mma_bf16(s[2 * nf2 + 1], qh[ks], bh2, bh3);
                mma_bf16(s[2 * nf2 + 1], qh[ks], bl2, bl3);
                mma_bf16(s[2 * nf2 + 1], ql[ks], bh2, bh3);
            }
        }

        // ---- causal mask on diagonal tile ----
        if (jt == qt) {
            #pragma unroll
            for (int nf = 0; nf < 8; nf++) {
                const int c0 = nf * 8 + qd;
                const int r0 = w * 16 + g;
                if (c0     > r0)     s[nf][0] = -1e30f;
                if (c0 + 1 > r0)     s[nf][1] = -1e30f;
                if (c0     > r0 + 8) s[nf][2] = -1e30f;
                if (c0 + 1 > r0 + 8) s[nf][3] = -1e30f;
            }
        }

        // ---- online softmax ----
        float mx0 = -1e30f, mx1 = -1e30f;
        #pragma unroll
        for (int nf = 0; nf < 8; nf++) {
            mx0 = fmaxf(mx0, fmaxf(s[nf][0], s[nf][1]));
            mx1 = fmaxf(mx1, fmaxf(s[nf][2], s[nf][3]));
        }
        mx0 = fmaxf(mx0, __shfl_xor_sync(0xffffffffu, mx0, 1));
        mx0 = fmaxf(mx0, __shfl_xor_sync(0xffffffffu, mx0, 2));
        mx1 = fmaxf(mx1, __shfl_xor_sync(0xffffffffu, mx1, 1));
        mx1 = fmaxf(mx1, __shfl_xor_sync(0xffffffffu, mx1, 2));
        const float mn0 = fmaxf(mrow[0], mx0);
        const float mn1 = fmaxf(mrow[1], mx1);
        const float a0  = __expf(mrow[0] - mn0);
        const float a1  = __expf(mrow[1] - mn1);
        mrow[0] = mn0; mrow[1] = mn1;

        float sum0 = 0.f, sum1 = 0.f;
        #pragma unroll
        for (int nf = 0; nf < 8; nf++) {
            s[nf][0] = __expf(s[nf][0] - mn0);
            s[nf][1] = __expf(s[nf][1] - mn0);
            s[nf][2] = __expf(s[nf][2] - mn1);
            s[nf][3] = __expf(s[nf][3] - mn1);
            sum0 += s[nf][0] + s[nf][1];
            sum1 += s[nf][2] + s[nf][3];
        }
        sum0 += __shfl_xor_sync(0xffffffffu, sum0, 1);
        sum0 += __shfl_xor_sync(0xffffffffu, sum0, 2);
        sum1 += __shfl_xor_sync(0xffffffffu, sum1, 1);
        sum1 += __shfl_xor_sync(0xffffffffu, sum1, 2);
        lrow[0] = lrow[0] * a0 + sum0;
        lrow[1] = lrow[1] * a1 + sum1;

        #pragma unroll
        for (int nf = 0; nf < 16; nf++) {
            O[nf][0] *= a0; O[nf][1] *= a0;
            O[nf][2] *= a1; O[nf][3] *= a1;
        }

        CP_WAIT(0);          // V arrived
        __syncthreads();

        // ---- O += P V : V B-frags via ldmatrix.trans on row-major V ----
        #pragma unroll
        for (int ks = 0; ks < 4; ks++) {
            u32 ph[4], pl[4];
            split_pair(s[2 * ks][0],     s[2 * ks][1],     ph[0], pl[0]);
            split_pair(s[2 * ks][2],     s[2 * ks][3],     ph[1], pl[1]);
            split_pair(s[2 * ks + 1][0], s[2 * ks + 1][1], ph[2], pl[2]);
            split_pair(s[2 * ks + 1][2], s[2 * ks + 1][3], ph[3], pl[3]);
            #pragma unroll
            for (int nf2 = 0; nf2 < 8; nf2++) {
                u32 bh0, bh1, bh2, bh3, bl0, bl1, bl2, bl3;
                ldsm4t(Vh_b + vb_off + ks * (16 * 272) + nf2 * 32, bh0, bh1, bh2, bh3);
                ldsm4t(Vl_b + vb_off + ks * (16 * 272) + nf2 * 32, bl0, bl1, bl2, bl3);
                mma_bf16(O[2 * nf2],     ph, bh0, bh1);
                mma_bf16(O[2 * nf2],     ph, bl0, bl1);
                mma_bf16(O[2 * nf2],     pl, bh0, bh1);
                mma_bf16(O[2 * nf2 + 1], ph, bh2, bh3);
                mma_bf16(O[2 * nf2 + 1], ph, bl2, bl3);
                mma_bf16(O[2 * nf2 + 1], pl, bh2, bh3);
            }
        }
    }

    // ---- epilogue: normalize + store fp32 ----
    const float inv0 = 1.0f / lrow[0];
    const float inv1 = 1.0f / lrow[1];
    const size_t r0 = (size_t)b * TT + i0 + w * 16 + g;
    #pragma unroll
    for (int nf = 0; nf < 16; nf++) {
        const int col = nf * 8 + qd;
        float2 v0 = make_float2(O[nf][0] * inv0, O[nf][1] * inv0);
        float2 v1 = make_float2(O[nf][2] * inv1, O[nf][3] * inv1);
        *reinterpret_cast<float2*>(out + r0 * HD + col)       = v0;
        *reinterpret_cast<float2*>(out + (r0 + 8) * HD + col) = v1;
    }
}

// ---------------------------------------------------------------------------
extern "C" void kernel_launch(void* const* d_in, const int* in_sizes, int n_in,
                              void* d_out, int out_size)
{
    const float* X  = (const float*)d_in[0];   // [8,2048,1024]
    const float* Wq = (const float*)d_in[1];   // [1024,128]
    const float* Wk = (const float*)d_in[2];
    const float* Wv = (const float*)d_in[3];
    float* out = (float*)d_out;                // [8,2048,128]
    (void)in_sizes; (void)n_in; (void)out_size;

    cudaFuncSetAttribute(qkv_mma,
        cudaFuncAttributeMaxDynamicSharedMemorySize, GEMM_SMEM);
    cudaFuncSetAttribute(attn_kernel,
        cudaFuncAttributeMaxDynamicSharedMemorySize, ATTN_SMEM);

    convert_w<<<dim3(HD / 32, CIN / 32, 3), dim3(32, 8)>>>(Wq, Wk, Wv);
    qkv_mma<<<dim3(3, BT / 128), 256, GEMM_SMEM>>>(X);
    attn_kernel<<<dim3(TT / 64, BB), 128, ATTN_SMEM>>>(out);
}

// round 7
// speedup vs baseline: 1.0366x; 1.0358x over previous
#include <cuda_runtime.h>
#include <cuda_bf16.h>
#include <cstdint>

#define BB   8
#define TT   2048
#define CIN  1024
#define HD   128
#define BT   (BB*TT)          // 16384 rows

typedef unsigned int u32;

// ---------------------------------------------------------------------------
// Device scratch (static globals: allocation-guard safe). bf16 hi/lo splits.
// ---------------------------------------------------------------------------
__device__ __align__(256) __nv_bfloat16 gQh[(size_t)BT * HD];
__device__ __align__(256) __nv_bfloat16 gQl[(size_t)BT * HD];
__device__ __align__(256) __nv_bfloat16 gKh[(size_t)BT * HD];
__device__ __align__(256) __nv_bfloat16 gKl[(size_t)BT * HD];
__device__ __align__(256) __nv_bfloat16 gVh[(size_t)BT * HD];
__device__ __align__(256) __nv_bfloat16 gVl[(size_t)BT * HD];
__device__ __align__(256) __nv_bfloat16 gWh[3][HD * CIN];   // W^T hi [o][n][k]
__device__ __align__(256) __nv_bfloat16 gWl[3][HD * CIN];   // W^T lo

// ---------------------------------------------------------------------------
// Helpers
// ---------------------------------------------------------------------------
__device__ __forceinline__ u32 pack_bf16(float x, float y) {
    __nv_bfloat162 h = __floats2bfloat162_rn(x, y);
    return *reinterpret_cast<u32*>(&h);
}
__device__ __forceinline__ void split_pair(float x, float y, u32& hi, u32& lo) {
    float hx = __bfloat162float(__float2bfloat16(x));
    float hy = __bfloat162float(__float2bfloat16(y));
    hi = pack_bf16(hx, hy);
    lo = pack_bf16(x - hx, y - hy);
}
__device__ __forceinline__ void mma_bf16(float* d, const u32* a, u32 b0, u32 b1) {
    asm volatile(
        "mma.sync.aligned.m16n8k16.row.col.f32.bf16.bf16.f32 "
        "{%0,%1,%2,%3}, {%4,%5,%6,%7}, {%8,%9}, {%0,%1,%2,%3};"
        : "+f"(d[0]), "+f"(d[1]), "+f"(d[2]), "+f"(d[3])
        : "r"(a[0]), "r"(a[1]), "r"(a[2]), "r"(a[3]), "r"(b0), "r"(b1));
}
__device__ __forceinline__ u32 smem_u32(const void* p) {
    u32 a;
    asm("{ .reg .u64 t; cvta.to.shared.u64 t, %1; cvt.u32.u64 %0, t; }"
        : "=r"(a) : "l"(p));
    return a;
}
__device__ __forceinline__ void ldsm4(u32 a, u32& r0, u32& r1, u32& r2, u32& r3) {
    asm volatile("ldmatrix.sync.aligned.m8n8.x4.shared.b16 {%0,%1,%2,%3}, [%4];"
                 : "=r"(r0), "=r"(r1), "=r"(r2), "=r"(r3) : "r"(a));
}
__device__ __forceinline__ void ldsm4t(u32 a, u32& r0, u32& r1, u32& r2, u32& r3) {
    asm volatile("ldmatrix.sync.aligned.m8n8.x4.trans.shared.b16 {%0,%1,%2,%3}, [%4];"
                 : "=r"(r0), "=r"(r1), "=r"(r2), "=r"(r3) : "r"(a));
}
#define CP16(dst, src) \
    asm volatile("cp.async.cg.shared.global [%0], [%1], 16;" \
                 :: "r"(dst), "l"(src) : "memory")
#define CP_COMMIT() asm volatile("cp.async.commit_group;" ::: "memory")
#define CP_WAIT(n)  asm volatile("cp.async.wait_group %0;" :: "n"(n) : "memory")

// ---------------------------------------------------------------------------
// Kernel A: transpose + split weights via smem tile (coalesced both sides).
// ---------------------------------------------------------------------------
__global__ void convert_w(const float* __restrict__ Wq,
                          const float* __restrict__ Wk,
                          const float* __restrict__ Wv)
{
    __shared__ float tile[32][33];
    const int o  = blockIdx.z;
    const float* W = (o == 0) ? Wq : (o == 1 ? Wk : Wv);
    const int n0 = blockIdx.x * 32;
    const int k0 = blockIdx.y * 32;
    const int tx = threadIdx.x, ty = threadIdx.y;

    #pragma unroll
    for (int i = ty; i < 32; i += 8)
        tile[i][tx] = W[(size_t)(k0 + i) * HD + n0 + tx];
    __syncthreads();
    #pragma unroll
    for (int i = ty; i < 32; i += 8) {
        float w  = tile[tx][i];                   // k = k0+tx, n = n0+i
        float hh = __bfloat162float(__float2bfloat16(w));
        gWh[o][(size_t)(n0 + i) * CIN + k0 + tx] = __float2bfloat16(hh);
        gWl[o][(size_t)(n0 + i) * CIN + k0 + tx] = __float2bfloat16(w - hh);
    }
}

// ---------------------------------------------------------------------------
// Kernel B: QKV GEMM. BM=128, BN=128, BK=32; 8 warps (4 wm x 2 wn).
// grid(3, 128): o fastest -> 3 CTAs with same m run together (X L2 reuse).
// ldmatrix fragments + register prefetch of next X/W tiles. (unchanged)
// ---------------------------------------------------------------------------
#define GS 40   // smem k-stride (halves): 80B rows, 16B aligned, LDSM-conflict-free
#define GEMM_SMEM (4 * 128 * GS * 2)

__global__ __launch_bounds__(256) void qkv_mma(const float* __restrict__ X)
{
    extern __shared__ __nv_bfloat16 smg[];
    __nv_bfloat16* Xh = smg;
    __nv_bfloat16* Xl = Xh + 128 * GS;
    __nv_bfloat16* Wh = Xl + 128 * GS;
    __nv_bfloat16* Wl = Wh + 128 * GS;
    const u32 Xh_b = smem_u32(Xh), Xl_b = smem_u32(Xl);
    const u32 Wh_b = smem_u32(Wh), Wl_b = smem_u32(Wl);

    const int t    = threadIdx.x;
    const int lane = t & 31;
    const int wrp  = t >> 5;
    const int wm   = wrp >> 1;
    const int wn   = wrp & 1;
    const int g    = lane >> 2;
    const int qd   = (lane & 3) << 1;
    const int j    = lane >> 3;
    const int lr   = lane & 7;
    const int o    = blockIdx.x;
    const size_t m0 = (size_t)blockIdx.y * 128;

    u32 ga_off[2];
    #pragma unroll
    for (int mf = 0; mf < 2; mf++)
        ga_off[mf] = (wm * 32 + mf * 16 + ((j & 1) << 3) + lr) * 80 + ((j >> 1) << 4);
    const u32 gb_off = (wn * 64 + ((j >> 1) << 3) + lr) * 80 + ((j & 1) << 4);

    const __nv_bfloat16* Wgh = gWh[o];
    const __nv_bfloat16* Wgl = gWl[o];

    float acc[2][8][4];
    #pragma unroll
    for (int mf = 0; mf < 2; mf++)
        #pragma unroll
        for (int nf = 0; nf < 8; nf++)
            #pragma unroll
            for (int e = 0; e < 4; e++) acc[mf][nf][e] = 0.f;

    float4 xv[4];
    uint4  wvh[2], wvl[2];
    const int xr  = t >> 3;
    const int xc  = (t & 7) << 2;
    const int wn_ = t >> 2;
    const int wc  = (t & 3) << 3;

    #pragma unroll
    for (int i = 0; i < 4; i++)
        xv[i] = *reinterpret_cast<const float4*>(X + (m0 + xr + i * 32) * CIN + xc);
    #pragma unroll
    for (int i = 0; i < 2; i++) {
        wvh[i] = *reinterpret_cast<const uint4*>(&Wgh[(wn_ + i * 64) * CIN + wc]);
        wvl[i] = *reinterpret_cast<const uint4*>(&Wgl[(wn_ + i * 64) * CIN + wc]);
    }

    for (int it = 0; it < 32; it++) {
        __syncthreads();
        #pragma unroll
        for (int i = 0; i < 4; i++) {
            u32 h0, l0, h1, l1;
            split_pair(xv[i].x, xv[i].y, h0, l0);
            split_pair(xv[i].z, xv[i].w, h1, l1);
            const int r = xr + i * 32;
            *reinterpret_cast<u32*>(&Xh[r * GS + xc])     = h0;
            *reinterpret_cast<u32*>(&Xh[r * GS + xc + 2]) = h1;
            *reinterpret_cast<u32*>(&Xl[r * GS + xc])     = l0;
            *reinterpret_cast<u32*>(&Xl[r * GS + xc + 2]) = l1;
        }
        #pragma unroll
        for (int i = 0; i < 2; i++) {
            *reinterpret_cast<uint4*>(&Wh[(wn_ + i * 64) * GS + wc]) = wvh[i];
            *reinterpret_cast<uint4*>(&Wl[(wn_ + i * 64) * GS + wc]) = wvl[i];
        }
        __syncthreads();

        if (it < 31) {
            const int k1 = (it + 1) * 32;
            #pragma unroll
            for (int i = 0; i < 4; i++)
                xv[i] = *reinterpret_cast<const float4*>(X + (m0 + xr + i * 32) * CIN + k1 + xc);
            #pragma unroll
            for (int i = 0; i < 2; i++) {
                wvh[i] = *reinterpret_cast<const uint4*>(&Wgh[(wn_ + i * 64) * CIN + k1 + wc]);
                wvl[i] = *reinterpret_cast<const uint4*>(&Wgl[(wn_ + i * 64) * CIN + k1 + wc]);
            }
        }

        #pragma unroll
        for (int ks = 0; ks < 2; ks++) {
            u32 ah[2][4], al[2][4];
            #pragma unroll
            for (int mf = 0; mf < 2; mf++) {
                ldsm4(Xh_b + ga_off[mf] + ks * 32, ah[mf][0], ah[mf][1], ah[mf][2], ah[mf][3]);
                ldsm4(Xl_b + ga_off[mf] + ks * 32, al[mf][0], al[mf][1], al[mf][2], al[mf][3]);
            }
            #pragma unroll
            for (int nf2 = 0; nf2 < 4; nf2++) {
                u32 bh0, bh1, bh2, bh3, bl0, bl1, bl2, bl3;
                ldsm4(Wh_b + gb_off + nf2 * (16 * 80) + ks * 32, bh0, bh1, bh2, bh3);
                ldsm4(Wl_b + gb_off + nf2 * (16 * 80) + ks * 32, bl0, bl1, bl2, bl3);
                #pragma unroll
                for (int mf = 0; mf < 2; mf++) {
                    mma_bf16(acc[mf][2 * nf2],     ah[mf], bh0, bh1);
                    mma_bf16(acc[mf][2 * nf2],     ah[mf], bl0, bl1);
                    mma_bf16(acc[mf][2 * nf2],     al[mf], bh0, bh1);
                    mma_bf16(acc[mf][2 * nf2 + 1], ah[mf], bh2, bh3);
                    mma_bf16(acc[mf][2 * nf2 + 1], ah[mf], bl2, bl3);
                    mma_bf16(acc[mf][2 * nf2 + 1], al[mf], bh2, bh3);
                }
            }
        }
    }

    const float scale = (o == 0) ? 0.03125f : 1.0f;
    __nv_bfloat16* Gh = (o == 0) ? gQh : (o == 1 ? gKh : gVh);
    __nv_bfloat16* Gl = (o == 0) ? gQl : (o == 1 ? gKl : gVl);
    #pragma unroll
    for (int mf = 0; mf < 2; mf++) {
        const size_t r = m0 + wm * 32 + mf * 16 + g;
        #pragma unroll
        for (int nf = 0; nf < 8; nf++) {
            const int col = wn * 64 + nf * 8 + qd;
            u32 hi, lo;
            split_pair(acc[mf][nf][0] * scale, acc[mf][nf][1] * scale, hi, lo);
            *reinterpret_cast<u32*>(&Gh[r * HD + col]) = hi;
            *reinterpret_cast<u32*>(&Gl[r * HD + col]) = lo;
            split_pair(acc[mf][nf][2] * scale, acc[mf][nf][3] * scale, hi, lo);
            *reinterpret_cast<u32*>(&Gh[(r + 8) * HD + col]) = hi;
            *reinterpret_cast<u32*>(&Gl[(r + 8) * HD + col]) = lo;
        }
    }
}

// ---------------------------------------------------------------------------
// Kernel C: causal flash attention, cross-tile pipelined.
// K double-buffered (prefetch jt+1 during compute of jt); V single-buffered,
// issued at end of iter jt so its latency hides under S+softmax of jt+1.
// Q staged through K-stage-1 buffers pre-loop (dead before first prefetch).
// Uniform commit cadence (K-group then V-group per iter; empty groups legal)
// makes cp.async.wait_group(1) provide exactly the in-order guarantees needed.
// ---------------------------------------------------------------------------
#define AST 136                      // smem row stride in halves (272 B)
#define TILE_B (64 * AST * 2)        // one 64x128 bf16 tile: 17408 B
#define ATTN_SMEM (6 * TILE_B)       // Kh0 Kl0 Kh1 Kl1 Vh Vl = 104448 B

__device__ __forceinline__ void cp_tile64(u32 dst, const __nv_bfloat16* src, int t)
{
    #pragma unroll
    for (int i = 0; i < 8; i++) {
        const int c   = t + i * 128;
        const int row = c >> 4;
        const int col = c & 15;
        CP16(dst + row * 272 + col * 16, src + row * 128 + col * 8);
    }
}

__global__ __launch_bounds__(128) void attn_kernel(float* __restrict__ out)
{
    extern __shared__ __nv_bfloat16 sma[];
    const u32 base  = smem_u32(sma);
    const u32 Kh_s0 = base,              Kl_s0 = base + TILE_B;
    const u32 Kh_s1 = base + 2*TILE_B,   Kl_s1 = base + 3*TILE_B;
    const u32 Vh_b  = base + 4*TILE_B,   Vl_b  = base + 5*TILE_B;

    const int t    = threadIdx.x;
    const int lane = t & 31;
    const int w    = t >> 5;
    const int g    = lane >> 2;
    const int qd   = (lane & 3) << 1;
    const int j    = lane >> 3;
    const int lr   = lane & 7;
    const int b    = blockIdx.y;
    const int qt   = (int)gridDim.x - 1 - (int)blockIdx.x;   // heavy first
    const int i0   = qt * 64;

    // ldmatrix byte offsets (stride 272B)
    const u32 a_off  = (w * 16 + ((j & 1) << 3) + lr) * 272 + ((j >> 1) << 4);
    const u32 kb_off = (((j >> 1) << 3) + lr) * 272 + ((j & 1) << 4);
    const u32 vb_off = (((j & 1) << 3) + lr) * 272 + ((j >> 1) << 4);

    // ---- prologue: Q -> K-stage-1 buffers; K(0) -> stage 0; V(0) -> Vbuf ----
    cp_tile64(Kh_s0, gKh + ((size_t)b * TT) * HD + (size_t)0, t);   // K(0)
    cp_tile64(Kl_s0, gKl + ((size_t)b * TT) * HD, t);
    cp_tile64(Vh_b,  gVh + ((size_t)b * TT) * HD, t);               // V(0)
    cp_tile64(Vl_b,  gVl + ((size_t)b * TT) * HD, t);
    cp_tile64(Kh_s1, gQh + ((size_t)b * TT + i0) * HD, t);          // Q
    cp_tile64(Kl_s1, gQl + ((size_t)b * TT + i0) * HD, t);
    CP_COMMIT();
    CP_WAIT(0);
    __syncthreads();

    u32 qh[8][4], ql[8][4];
    #pragma unroll
    for (int ks = 0; ks < 8; ks++) {
        ldsm4(Kh_s1 + a_off + ks * 32, qh[ks][0], qh[ks][1], qh[ks][2], qh[ks][3]);
        ldsm4(Kl_s1 + a_off + ks * 32, ql[ks][0], ql[ks][1], ql[ks][2], ql[ks][3]);
    }

    float O[16][4];
    #pragma unroll
    for (int nf = 0; nf < 16; nf++)
        #pragma unroll
        for (int e = 0; e < 4; e++) O[nf][e] = 0.f;
    float mrow[2] = {-1e30f, -1e30f};
    float lrow[2] = {0.f, 0.f};

    for (int jt = 0; jt <= qt; jt++) {
        const int stage = jt & 1;
        const u32 kh = stage ? Kh_s1 : Kh_s0;
        const u32 kl = stage ? Kl_s1 : Kl_s0;

        CP_WAIT(1);          // K(jt) complete (V(jt) group may still be in flight)
        __syncthreads();     // also orders Q-frag extraction / prior-stage reads

        // prefetch K(jt+1) into the other stage; latency hides under S+softmax+PV
        if (jt < qt) {
            const size_t roff = ((size_t)b * TT + (jt + 1) * 64) * HD;
            cp_tile64(stage ? Kh_s0 : Kh_s1, gKh + roff, t);
            cp_tile64(stage ? Kl_s0 : Kl_s1, gKl + roff, t);
        }
        CP_COMMIT();         // empty group on last iter keeps wait cadence uniform

        // ---- S = Q K^T (hi*hi + hi*lo + lo*hi) ----
        float s[8][4];
        #pragma unroll
        for (int nf = 0; nf < 8; nf++)
            #pragma unroll
            for (int e = 0; e < 4; e++) s[nf][e] = 0.f;

        #pragma unroll
        for (int ks = 0; ks < 8; ks++) {
            #pragma unroll
            for (int nf2 = 0; nf2 < 4; nf2++) {
                u32 bh0, bh1, bh2, bh3, bl0, bl1, bl2, bl3;
                ldsm4(kh + kb_off + nf2 * (16 * 272) + ks * 32, bh0, bh1, bh2, bh3);
                ldsm4(kl + kb_off + nf2 * (16 * 272) + ks * 32, bl0, bl1, bl2, bl3);
                mma_bf16(s[2 * nf2],     qh[ks], bh0, bh1);
                mma_bf16(s[2 * nf2],     qh[ks], bl0, bl1);
                mma_bf16(s[2 * nf2],     ql[ks], bh0, bh1);
                mma_bf16(s[2 * nf2 + 1], qh[ks], bh2, bh3);
                mma_bf16(s[2 * nf2 + 1], qh[ks], bl2, bl3);
                mma_bf16(s[2 * nf2 + 1], ql[ks], bh2, bh3);
            }
        }

        // ---- causal mask on diagonal tile ----
        if (jt == qt) {
            #pragma unroll
            for (int nf = 0; nf < 8; nf++) {
                const int c0 = nf * 8 + qd;
                const int r0 = w * 16 + g;
                if (c0     > r0)     s[nf][0] = -1e30f;
                if (c0 + 1 > r0)     s[nf][1] = -1e30f;
                if (c0     > r0 + 8) s[nf][2] = -1e30f;
                if (c0 + 1 > r0 + 8) s[nf][3] = -1e30f;
            }
        }

        // ---- online softmax ----
        float mx0 = -1e30f, mx1 = -1e30f;
        #pragma unroll
        for (int nf = 0; nf < 8; nf++) {
            mx0 = fmaxf(mx0, fmaxf(s[nf][0], s[nf][1]));
            mx1 = fmaxf(mx1, fmaxf(s[nf][2], s[nf][3]));
        }
        mx0 = fmaxf(mx0, __shfl_xor_sync(0xffffffffu, mx0, 1));
        mx0 = fmaxf(mx0, __shfl_xor_sync(0xffffffffu, mx0, 2));
        mx1 = fmaxf(mx1, __shfl_xor_sync(0xffffffffu, mx1, 1));
        mx1 = fmaxf(mx1, __shfl_xor_sync(0xffffffffu, mx1, 2));
        const float mn0 = fmaxf(mrow[0], mx0);
        const float mn1 = fmaxf(mrow[1], mx1);
        const float a0  = __expf(mrow[0] - mn0);
        const float a1  = __expf(mrow[1] - mn1);
        mrow[0] = mn0; mrow[1] = mn1;

        float sum0 = 0.f, sum1 = 0.f;
        #pragma unroll
        for (int nf = 0; nf < 8; nf++) {
            s[nf][0] = __expf(s[nf][0] - mn0);
            s[nf][1] = __expf(s[nf][1] - mn0);
            s[nf][2] = __expf(s[nf][2] - mn1);
            s[nf][3] = __expf(s[nf][3] - mn1);
            sum0 += s[nf][0] + s[nf][1];
            sum1 += s[nf][2] + s[nf][3];
        }
        sum0 += __shfl_xor_sync(0xffffffffu, sum0, 1);
        sum0 += __shfl_xor_sync(0xffffffffu, sum0, 2);
        sum1 += __shfl_xor_sync(0xffffffffu, sum1, 1);
        sum1 += __shfl_xor_sync(0xffffffffu, sum1, 2);
        lrow[0] = lrow[0] * a0 + sum0;
        lrow[1] = lrow[1] * a1 + sum1;

        #pragma unroll
        for (int nf = 0; nf < 16; nf++) {
            O[nf][0] *= a0; O[nf][1] *= a0;
            O[nf][2] *= a1; O[nf][3] *= a1;
        }

        CP_WAIT(1);          // V(jt) complete (K(jt+1) group may still be in flight)
        __syncthreads();

        // ---- O += P V : V B-frags via ldmatrix.trans on row-major V ----
        #pragma unroll
        for (int ks = 0; ks < 4; ks++) {
            u32 ph[4], pl[4];
            split_pair(s[2 * ks][0],     s[2 * ks][1],     ph[0], pl[0]);
            split_pair(s[2 * ks][2],     s[2 * ks][3],     ph[1], pl[1]);
            split_pair(s[2 * ks + 1][0], s[2 * ks + 1][1], ph[2], pl[2]);
            split_pair(s[2 * ks + 1][2], s[2 * ks + 1][3], ph[3], pl[3]);
            #pragma unroll
            for (int nf2 = 0; nf2 < 8; nf2++) {
                u32 bh0, bh1, bh2, bh3, bl0, bl1, bl2, bl3;
                ldsm4t(Vh_b + vb_off + ks * (16 * 272) + nf2 * 32, bh0, bh1, bh2, bh3);
                ldsm4t(Vl_b + vb_off + ks * (16 * 272) + nf2 * 32, bl0, bl1, bl2, bl3);
                mma_bf16(O[2 * nf2],     ph, bh0, bh1);
                mma_bf16(O[2 * nf2],     ph, bl0, bl1);
                mma_bf16(O[2 * nf2],     pl, bh0, bh1);
                mma_bf16(O[2 * nf2 + 1], ph, bh2, bh3);
                mma_bf16(O[2 * nf2 + 1], ph, bl2, bl3);
                mma_bf16(O[2 * nf2 + 1], pl, bh2, bh3);
            }
        }

        __syncthreads();     // all warps done reading V(jt) before overwrite
        if (jt < qt) {
            const size_t roff = ((size_t)b * TT + (jt + 1) * 64) * HD;
            cp_tile64(Vh_b, gVh + roff, t);     // hides under S+softmax of jt+1
            cp_tile64(Vl_b, gVl + roff, t);
        }
        CP_COMMIT();
    }

    // ---- epilogue: normalize + store fp32 ----
    const float inv0 = 1.0f / lrow[0];
    const float inv1 = 1.0f / lrow[1];
    const size_t r0 = (size_t)b * TT + i0 + w * 16 + g;
    #pragma unroll
    for (int nf = 0; nf < 16; nf++) {
        const int col = nf * 8 + qd;
        float2 v0 = make_float2(O[nf][0] * inv0, O[nf][1] * inv0);
        float2 v1 = make_float2(O[nf][2] * inv1, O[nf][3] * inv1);
        *reinterpret_cast<float2*>(out + r0 * HD + col)       = v0;
        *reinterpret_cast<float2*>(out + (r0 + 8) * HD + col) = v1;
    }
}

// ---------------------------------------------------------------------------
extern "C" void kernel_launch(void* const* d_in, const int* in_sizes, int n_in,
                              void* d_out, int out_size)
{
    const float* X  = (const float*)d_in[0];   // [8,2048,1024]
    const float* Wq = (const float*)d_in[1];   // [1024,128]
    const float* Wk = (const float*)d_in[2];
    const float* Wv = (const float*)d_in[3];
    float* out = (float*)d_out;                // [8,2048,128]
    (void)in_sizes; (void)n_in; (void)out_size;

    cudaFuncSetAttribute(qkv_mma,
        cudaFuncAttributeMaxDynamicSharedMemorySize, GEMM_SMEM);
    cudaFuncSetAttribute(attn_kernel,
        cudaFuncAttributeMaxDynamicSharedMemorySize, ATTN_SMEM);

    convert_w<<<dim3(HD / 32, CIN / 32, 3), dim3(32, 8)>>>(Wq, Wk, Wv);
    qkv_mma<<<dim3(3, BT / 128), 256, GEMM_SMEM>>>(X);
    attn_kernel<<<dim3(TT / 64, BB), 128, ATTN_SMEM>>>(out);
}

// round 8
// speedup vs baseline: 1.8037x; 1.7400x over previous
#include <cuda_runtime.h>
#include <cuda_fp16.h>
#include <cstdint>

#define BB   8
#define TT   2048
#define CIN  1024
#define HD   128
#define BT   (BB*TT)          // 16384 rows

typedef unsigned int u32;

// ---------------------------------------------------------------------------
// Device scratch (static globals: allocation-guard safe). fp16.
// ---------------------------------------------------------------------------
__device__ __align__(256) __half gQ[(size_t)BT * HD];
__device__ __align__(256) __half gK[(size_t)BT * HD];
__device__ __align__(256) __half gV[(size_t)BT * HD];
__device__ __align__(256) __half gWh[3][HD * CIN];   // W^T hi [o][n][k]
__device__ __align__(256) __half gWl[3][HD * CIN];   // W^T lo

// ---------------------------------------------------------------------------
// Helpers
// ---------------------------------------------------------------------------
__device__ __forceinline__ u32 pack_half2(float x, float y) {
    __half2 h = __floats2half2_rn(x, y);
    return *reinterpret_cast<u32*>(&h);
}
__device__ __forceinline__ void mma_f16(float* d, const u32* a, u32 b0, u32 b1) {
    asm volatile(
        "mma.sync.aligned.m16n8k16.row.col.f32.f16.f16.f32 "
        "{%0,%1,%2,%3}, {%4,%5,%6,%7}, {%8,%9}, {%0,%1,%2,%3};"
        : "+f"(d[0]), "+f"(d[1]), "+f"(d[2]), "+f"(d[3])
        : "r"(a[0]), "r"(a[1]), "r"(a[2]), "r"(a[3]), "r"(b0), "r"(b1));
}
__device__ __forceinline__ u32 smem_u32(const void* p) {
    u32 a;
    asm("{ .reg .u64 t; cvta.to.shared.u64 t, %1; cvt.u32.u64 %0, t; }"
        : "=r"(a) : "l"(p));
    return a;
}
__device__ __forceinline__ void ldsm4(u32 a, u32& r0, u32& r1, u32& r2, u32& r3) {
    asm volatile("ldmatrix.sync.aligned.m8n8.x4.shared.b16 {%0,%1,%2,%3}, [%4];"
                 : "=r"(r0), "=r"(r1), "=r"(r2), "=r"(r3) : "r"(a));
}
__device__ __forceinline__ void ldsm4t(u32 a, u32& r0, u32& r1, u32& r2, u32& r3) {
    asm volatile("ldmatrix.sync.aligned.m8n8.x4.trans.shared.b16 {%0,%1,%2,%3}, [%4];"
                 : "=r"(r0), "=r"(r1), "=r"(r2), "=r"(r3) : "r"(a));
}
#define CP16(dst, src) \
    asm volatile("cp.async.cg.shared.global [%0], [%1], 16;" \
                 :: "r"(dst), "l"(src) : "memory")
#define CP_COMMIT() asm volatile("cp.async.commit_group;" ::: "memory")
#define CP_WAIT(n)  asm volatile("cp.async.wait_group %0;" :: "n"(n) : "memory")

// ---------------------------------------------------------------------------
// Kernel A: transpose + split weights via smem tile (coalesced both sides).
// ---------------------------------------------------------------------------
__global__ void convert_w(const float* __restrict__ Wq,
                          const float* __restrict__ Wk,
                          const float* __restrict__ Wv)
{
    __shared__ float tile[32][33];
    const int o  = blockIdx.z;
    const float* W = (o == 0) ? Wq : (o == 1 ? Wk : Wv);
    const int n0 = blockIdx.x * 32;
    const int k0 = blockIdx.y * 32;
    const int tx = threadIdx.x, ty = threadIdx.y;

    #pragma unroll
    for (int i = ty; i < 32; i += 8)
        tile[i][tx] = W[(size_t)(k0 + i) * HD + n0 + tx];
    __syncthreads();
    #pragma unroll
    for (int i = ty; i < 32; i += 8) {
        float w  = tile[tx][i];                   // k = k0+tx, n = n0+i
        __half hh = __float2half_rn(w);
        gWh[o][(size_t)(n0 + i) * CIN + k0 + tx] = hh;
        gWl[o][(size_t)(n0 + i) * CIN + k0 + tx] = __float2half_rn(w - __half2float(hh));
    }
}

// ---------------------------------------------------------------------------
// Kernel B: QKV GEMM. BM=128, BN=128, BK=32; 8 warps (4 wm x 2 wn).
// grid(3, 128): o fastest -> 3 CTAs with same m run together (X L2 reuse).
// fp16: Y = X16 @ (Wh + Wl).  2 MMAs per slice (X residual dropped).
// ---------------------------------------------------------------------------
#define GS 40   // smem k-stride (halves): 80B rows, 16B aligned, LDSM-conflict-free
#define GEMM_SMEM (3 * 128 * GS * 2)

__global__ __launch_bounds__(256) void qkv_mma(const float* __restrict__ X)
{
    extern __shared__ __half smg[];
    __half* Xs = smg;                 // [128][GS]
    __half* Wh = Xs + 128 * GS;       // [128 n][GS]
    __half* Wl = Wh + 128 * GS;
    const u32 Xs_b = smem_u32(Xs);
    const u32 Wh_b = smem_u32(Wh), Wl_b = smem_u32(Wl);

    const int t    = threadIdx.x;
    const int lane = t & 31;
    const int wrp  = t >> 5;
    const int wm   = wrp >> 1;
    const int wn   = wrp & 1;
    const int g    = lane >> 2;
    const int qd   = (lane & 3) << 1;
    const int j    = lane >> 3;
    const int lr   = lane & 7;
    const int o    = blockIdx.x;
    const size_t m0 = (size_t)blockIdx.y * 128;

    u32 ga_off[2];
    #pragma unroll
    for (int mf = 0; mf < 2; mf++)
        ga_off[mf] = (wm * 32 + mf * 16 + ((j & 1) << 3) + lr) * 80 + ((j >> 1) << 4);
    const u32 gb_off = (wn * 64 + ((j >> 1) << 3) + lr) * 80 + ((j & 1) << 4);

    const __half* Wgh = gWh[o];
    const __half* Wgl = gWl[o];

    float acc[2][8][4];
    #pragma unroll
    for (int mf = 0; mf < 2; mf++)
        #pragma unroll
        for (int nf = 0; nf < 8; nf++)
            #pragma unroll
            for (int e = 0; e < 4; e++) acc[mf][nf][e] = 0.f;

    float4 xv[4];
    uint4  wvh[2], wvl[2];
    const int xr  = t >> 3;
    const int xc  = (t & 7) << 2;
    const int wn_ = t >> 2;
    const int wc  = (t & 3) << 3;

    #pragma unroll
    for (int i = 0; i < 4; i++)
        xv[i] = *reinterpret_cast<const float4*>(X + (m0 + xr + i * 32) * CIN + xc);
    #pragma unroll
    for (int i = 0; i < 2; i++) {
        wvh[i] = *reinterpret_cast<const uint4*>(&Wgh[(wn_ + i * 64) * CIN + wc]);
        wvl[i] = *reinterpret_cast<const uint4*>(&Wgl[(wn_ + i * 64) * CIN + wc]);
    }

    for (int it = 0; it < 32; it++) {
        __syncthreads();
        #pragma unroll
        for (int i = 0; i < 4; i++) {
            const int r = xr + i * 32;
            *reinterpret_cast<u32*>(&Xs[r * GS + xc])     = pack_half2(xv[i].x, xv[i].y);
            *reinterpret_cast<u32*>(&Xs[r * GS + xc + 2]) = pack_half2(xv[i].z, xv[i].w);
        }
        #pragma unroll
        for (int i = 0; i < 2; i++) {
            *reinterpret_cast<uint4*>(&Wh[(wn_ + i * 64) * GS + wc]) = wvh[i];
            *reinterpret_cast<uint4*>(&Wl[(wn_ + i * 64) * GS + wc]) = wvl[i];
        }
        __syncthreads();

        if (it < 31) {
            const int k1 = (it + 1) * 32;
            #pragma unroll
            for (int i = 0; i < 4; i++)
                xv[i] = *reinterpret_cast<const float4*>(X + (m0 + xr + i * 32) * CIN + k1 + xc);
            #pragma unroll
            for (int i = 0; i < 2; i++) {
                wvh[i] = *reinterpret_cast<const uint4*>(&Wgh[(wn_ + i * 64) * CIN + k1 + wc]);
                wvl[i] = *reinterpret_cast<const uint4*>(&Wgl[(wn_ + i * 64) * CIN + k1 + wc]);
            }
        }

        #pragma unroll
        for (int ks = 0; ks < 2; ks++) {
            u32 ah[2][4];
            #pragma unroll
            for (int mf = 0; mf < 2; mf++)
                ldsm4(Xs_b + ga_off[mf] + ks * 32, ah[mf][0], ah[mf][1], ah[mf][2], ah[mf][3]);
            #pragma unroll
            for (int nf2 = 0; nf2 < 4; nf2++) {
                u32 bh0, bh1, bh2, bh3, bl0, bl1, bl2, bl3;
                ldsm4(Wh_b + gb_off + nf2 * (16 * 80) + ks * 32, bh0, bh1, bh2, bh3);
                ldsm4(Wl_b + gb_off + nf2 * (16 * 80) + ks * 32, bl0, bl1, bl2, bl3);
                #pragma unroll
                for (int mf = 0; mf < 2; mf++) {
                    mma_f16(acc[mf][2 * nf2],     ah[mf], bh0, bh1);
                    mma_f16(acc[mf][2 * nf2 + 1], ah[mf], bh2, bh3);
                    mma_f16(acc[mf][2 * nf2],     ah[mf], bl0, bl1);
                    mma_f16(acc[mf][2 * nf2 + 1], ah[mf], bl2, bl3);
                }
            }
        }
    }

    // Epilogue: scale Q by 1/sqrt(1024), round to fp16 globals
    const float scale = (o == 0) ? 0.03125f : 1.0f;
    __half* G = (o == 0) ? gQ : (o == 1 ? gK : gV);
    #pragma unroll
    for (int mf = 0; mf < 2; mf++) {
        const size_t r = m0 + wm * 32 + mf * 16 + g;
        #pragma unroll
        for (int nf = 0; nf < 8; nf++) {
            const int col = wn * 64 + nf * 8 + qd;
            *reinterpret_cast<u32*>(&G[r * HD + col]) =
                pack_half2(acc[mf][nf][0] * scale, acc[mf][nf][1] * scale);
            *reinterpret_cast<u32*>(&G[(r + 8) * HD + col]) =
                pack_half2(acc[mf][nf][2] * scale, acc[mf][nf][3] * scale);
        }
    }
}

// ---------------------------------------------------------------------------
// Kernel C: causal flash attention, fp16 single-term, cross-tile pipelined.
// S = Q@K^T (1 MMA/slice), O = P@V (1 MMA/slice). K double-buffered,
// V single-buffered issued at end of prior iter. 51KB smem -> 3-4 CTAs/SM.
// ---------------------------------------------------------------------------
#define AST 136                      // smem row stride in halves (272 B)
#define TILE_B (64 * AST * 2)        // one 64x128 fp16 tile: 17408 B
#define ATTN_SMEM (3 * TILE_B)       // K0 K1 V = 52224 B

__device__ __forceinline__ void cp_tile64(u32 dst, const __half* src, int t)
{
    #pragma unroll
    for (int i = 0; i < 8; i++) {
        const int c   = t + i * 128;
        const int row = c >> 4;
        const int col = c & 15;
        CP16(dst + row * 272 + col * 16, src + row * 128 + col * 8);
    }
}

__global__ __launch_bounds__(128, 3) void attn_kernel(float* __restrict__ out)
{
    extern __shared__ __half sma[];
    const u32 base = smem_u32(sma);
    const u32 K_s0 = base;
    const u32 K_s1 = base + TILE_B;
    const u32 V_b  = base + 2 * TILE_B;

    const int t    = threadIdx.x;
    const int lane = t & 31;
    const int w    = t >> 5;
    const int g    = lane >> 2;
    const int qd   = (lane & 3) << 1;
    const int j    = lane >> 3;
    const int lr   = lane & 7;
    const int b    = blockIdx.y;
    const int qt   = (int)gridDim.x - 1 - (int)blockIdx.x;   // heavy first
    const int i0   = qt * 64;

    // ldmatrix byte offsets (stride 272B)
    const u32 a_off  = (w * 16 + ((j & 1) << 3) + lr) * 272 + ((j >> 1) << 4);
    const u32 kb_off = (((j >> 1) << 3) + lr) * 272 + ((j & 1) << 4);
    const u32 vb_off = (((j & 1) << 3) + lr) * 272 + ((j >> 1) << 4);

    // ---- prologue: K(0)->s0, V(0)->V, Q staged through s1 ----
    cp_tile64(K_s0, gK + ((size_t)b * TT) * HD, t);
    cp_tile64(V_b,  gV + ((size_t)b * TT) * HD, t);
    cp_tile64(K_s1, gQ + ((size_t)b * TT + i0) * HD, t);
    CP_COMMIT();
    CP_WAIT(0);
    __syncthreads();

    u32 qh[8][4];
    #pragma unroll
    for (int ks = 0; ks < 8; ks++)
        ldsm4(K_s1 + a_off + ks * 32, qh[ks][0], qh[ks][1], qh[ks][2], qh[ks][3]);

    float O[16][4];
    #pragma unroll
    for (int nf = 0; nf < 16; nf++)
        #pragma unroll
        for (int e = 0; e < 4; e++) O[nf][e] = 0.f;
    float mrow[2] = {-1e30f, -1e30f};
    float lrow[2] = {0.f, 0.f};

    for (int jt = 0; jt <= qt; jt++) {
        const int stage = jt & 1;
        const u32 kh = stage ? K_s1 : K_s0;

        CP_WAIT(1);          // K(jt) complete (V(jt) may still be in flight)
        __syncthreads();

        // prefetch K(jt+1) into the other stage
        if (jt < qt)
            cp_tile64(stage ? K_s0 : K_s1,
                      gK + ((size_t)b * TT + (jt + 1) * 64) * HD, t);
        CP_COMMIT();         // empty group on last iter keeps cadence uniform

        // ---- S = Q K^T (single term) ----
        float s[8][4];
        #pragma unroll
        for (int nf = 0; nf < 8; nf++)
            #pragma unroll
            for (int e = 0; e < 4; e++) s[nf][e] = 0.f;

        #pragma unroll
        for (int ks = 0; ks < 8; ks++) {
            #pragma unroll
            for (int nf2 = 0; nf2 < 4; nf2++) {
                u32 b0, b1, b2, b3;
                ldsm4(kh + kb_off + nf2 * (16 * 272) + ks * 32, b0, b1, b2, b3);
                mma_f16(s[2 * nf2],     qh[ks], b0, b1);
                mma_f16(s[2 * nf2 + 1], qh[ks], b2, b3);
            }
        }

        // ---- causal mask on diagonal tile ----
        if (jt == qt) {
            #pragma unroll
            for (int nf = 0; nf < 8; nf++) {
                const int c0 = nf * 8 + qd;
                const int r0 = w * 16 + g;
                if (c0     > r0)     s[nf][0] = -1e30f;
                if (c0 + 1 > r0)     s[nf][1] = -1e30f;
                if (c0     > r0 + 8) s[nf][2] = -1e30f;
                if (c0 + 1 > r0 + 8) s[nf][3] = -1e30f;
            }
        }

        // ---- online softmax ----
        float mx0 = -1e30f, mx1 = -1e30f;
        #pragma unroll
        for (int nf = 0; nf < 8; nf++) {
            mx0 = fmaxf(mx0, fmaxf(s[nf][0], s[nf][1]));
            mx1 = fmaxf(mx1, fmaxf(s[nf][2], s[nf][3]));
        }
        mx0 = fmaxf(mx0, __shfl_xor_sync(0xffffffffu, mx0, 1));
        mx0 = fmaxf(mx0, __shfl_xor_sync(0xffffffffu, mx0, 2));
        mx1 = fmaxf(mx1, __shfl_xor_sync(0xffffffffu, mx1, 1));
        mx1 = fmaxf(mx1, __shfl_xor_sync(0xffffffffu, mx1, 2));
        const float mn0 = fmaxf(mrow[0], mx0);
        const float mn1 = fmaxf(mrow[1], mx1);
        const float a0  = __expf(mrow[0] - mn0);
        const float a1  = __expf(mrow[1] - mn1);
        mrow[0] = mn0; mrow[1] = mn1;

        float sum0 = 0.f, sum1 = 0.f;
        #pragma unroll
        for (int nf = 0; nf < 8; nf++) {
            s[nf][0] = __expf(s[nf][0] - mn0);
            s[nf][1] = __expf(s[nf][1] - mn0);
            s[nf][2] = __expf(s[nf][2] - mn1);
            s[nf][3] = __expf(s[nf][3] - mn1);
            sum0 += s[nf][0] + s[nf][1];
            sum1 += s[nf][2] + s[nf][3];
        }
        sum0 += __shfl_xor_sync(0xffffffffu, sum0, 1);
        sum0 += __shfl_xor_sync(0xffffffffu, sum0, 2);
        sum1 += __shfl_xor_sync(0xffffffffu, sum1, 1);
        sum1 += __shfl_xor_sync(0xffffffffu, sum1, 2);
        lrow[0] = lrow[0] * a0 + sum0;
        lrow[1] = lrow[1] * a1 + sum1;

        #pragma unroll
        for (int nf = 0; nf < 16; nf++) {
            O[nf][0] *= a0; O[nf][1] *= a0;
            O[nf][2] *= a1; O[nf][3] *= a1;
        }

        CP_WAIT(1);          // V(jt) complete (K(jt+1) may still be in flight)
        __syncthreads();

        // ---- O += P V : P rounded to fp16, V B-frags via ldmatrix.trans ----
        #pragma unroll
        for (int ks = 0; ks < 4; ks++) {
            u32 ph[4];
            ph[0] = pack_half2(s[2 * ks][0],     s[2 * ks][1]);
            ph[1] = pack_half2(s[2 * ks][2],     s[2 * ks][3]);
            ph[2] = pack_half2(s[2 * ks + 1][0], s[2 * ks + 1][1]);
            ph[3] = pack_half2(s[2 * ks + 1][2], s[2 * ks + 1][3]);
            #pragma unroll
            for (int nf2 = 0; nf2 < 8; nf2++) {
                u32 b0, b1, b2, b3;
                ldsm4t(V_b + vb_off + ks * (16 * 272) + nf2 * 32, b0, b1, b2, b3);
                mma_f16(O[2 * nf2],     ph, b0, b1);
                mma_f16(O[2 * nf2 + 1], ph, b2, b3);
            }
        }

        __syncthreads();     // all warps done reading V(jt) before overwrite
        if (jt < qt)
            cp_tile64(V_b, gV + ((size_t)b * TT + (jt + 1) * 64) * HD, t);
        CP_COMMIT();
    }

    // ---- epilogue: normalize + store fp32 ----
    const float inv0 = 1.0f / lrow[0];
    const float inv1 = 1.0f / lrow[1];
    const size_t r0 = (size_t)b * TT + i0 + w * 16 + g;
    #pragma unroll
    for (int nf = 0; nf < 16; nf++) {
        const int col = nf * 8 + qd;
        float2 v0 = make_float2(O[nf][0] * inv0, O[nf][1] * inv0);
        float2 v1 = make_float2(O[nf][2] * inv1, O[nf][3] * inv1);
        *reinterpret_cast<float2*>(out + r0 * HD + col)       = v0;
        *reinterpret_cast<float2*>(out + (r0 + 8) * HD + col) = v1;
    }
}

// ---------------------------------------------------------------------------
extern "C" void kernel_launch(void* const* d_in, const int* in_sizes, int n_in,
                              void* d_out, int out_size)
{
    const float* X  = (const float*)d_in[0];   // [8,2048,1024]
    const float* Wq = (const float*)d_in[1];   // [1024,128]
    const float* Wk = (const float*)d_in[2];
    const float* Wv = (const float*)d_in[3];
    float* out = (float*)d_out;                // [8,2048,128]
    (void)in_sizes; (void)n_in; (void)out_size;

    cudaFuncSetAttribute(qkv_mma,
        cudaFuncAttributeMaxDynamicSharedMemorySize, GEMM_SMEM);
    cudaFuncSetAttribute(attn_kernel,
        cudaFuncAttributeMaxDynamicSharedMemorySize, ATTN_SMEM);

    convert_w<<<dim3(HD / 32, CIN / 32, 3), dim3(32, 8)>>>(Wq, Wk, Wv);
    qkv_mma<<<dim3(3, BT / 128), 256, GEMM_SMEM>>>(X);
    attn_kernel<<<dim3(TT / 64, BB), 128, ATTN_SMEM>>>(out);
}

// round 9
// speedup vs baseline: 2.3914x; 1.3258x over previous
#include <cuda_runtime.h>
#include <cuda_fp16.h>
#include <cstdint>

#define BB   8
#define TT   2048
#define CIN  1024
#define HD   128
#define BT   (BB*TT)          // 16384 rows

typedef unsigned int u32;

// ---------------------------------------------------------------------------
// Device scratch (static globals: allocation-guard safe). fp16.
// ---------------------------------------------------------------------------
__device__ __align__(256) __half gQ[(size_t)BT * HD];
__device__ __align__(256) __half gK[(size_t)BT * HD];
__device__ __align__(256) __half gV[(size_t)BT * HD];
__device__ __align__(256) __half gW[3][HD * CIN];    // W^T fp16 [o][n][k]

// ---------------------------------------------------------------------------
// Helpers
// ---------------------------------------------------------------------------
__device__ __forceinline__ u32 pack_half2(float x, float y) {
    __half2 h = __floats2half2_rn(x, y);
    return *reinterpret_cast<u32*>(&h);
}
__device__ __forceinline__ void mma_f16(float* d, const u32* a, u32 b0, u32 b1) {
    asm volatile(
        "mma.sync.aligned.m16n8k16.row.col.f32.f16.f16.f32 "
        "{%0,%1,%2,%3}, {%4,%5,%6,%7}, {%8,%9}, {%0,%1,%2,%3};"
        : "+f"(d[0]), "+f"(d[1]), "+f"(d[2]), "+f"(d[3])
        : "r"(a[0]), "r"(a[1]), "r"(a[2]), "r"(a[3]), "r"(b0), "r"(b1));
}
__device__ __forceinline__ u32 smem_u32(const void* p) {
    u32 a;
    asm("{ .reg .u64 t; cvta.to.shared.u64 t, %1; cvt.u32.u64 %0, t; }"
        : "=r"(a) : "l"(p));
    return a;
}
__device__ __forceinline__ void ldsm4(u32 a, u32& r0, u32& r1, u32& r2, u32& r3) {
    asm volatile("ldmatrix.sync.aligned.m8n8.x4.shared.b16 {%0,%1,%2,%3}, [%4];"
                 : "=r"(r0), "=r"(r1), "=r"(r2), "=r"(r3) : "r"(a));
}
__device__ __forceinline__ void ldsm4t(u32 a, u32& r0, u32& r1, u32& r2, u32& r3) {
    asm volatile("ldmatrix.sync.aligned.m8n8.x4.trans.shared.b16 {%0,%1,%2,%3}, [%4];"
                 : "=r"(r0), "=r"(r1), "=r"(r2), "=r"(r3) : "r"(a));
}
#define CP16(dst, src) \
    asm volatile("cp.async.cg.shared.global [%0], [%1], 16;" \
                 :: "r"(dst), "l"(src) : "memory")
#define CP_COMMIT() asm volatile("cp.async.commit_group;" ::: "memory")
#define CP_WAIT(n)  asm volatile("cp.async.wait_group %0;" :: "n"(n) : "memory")

// ---------------------------------------------------------------------------
// Kernel A: transpose weights to fp16 via smem tile (coalesced both sides).
// ---------------------------------------------------------------------------
__global__ void convert_w(const float* __restrict__ Wq,
                          const float* __restrict__ Wk,
                          const float* __restrict__ Wv)
{
    __shared__ float tile[32][33];
    const int o  = blockIdx.z;
    const float* W = (o == 0) ? Wq : (o == 1 ? Wk : Wv);
    const int n0 = blockIdx.x * 32;
    const int k0 = blockIdx.y * 32;
    const int tx = threadIdx.x, ty = threadIdx.y;

    #pragma unroll
    for (int i = ty; i < 32; i += 8)
        tile[i][tx] = W[(size_t)(k0 + i) * HD + n0 + tx];
    __syncthreads();
    #pragma unroll
    for (int i = ty; i < 32; i += 8)
        gW[o][(size_t)(n0 + i) * CIN + k0 + tx] = __float2half_rn(tile[tx][i]);
}

// ---------------------------------------------------------------------------
// Kernel B: QKV GEMM. BM=128, BN=128, BK=32; 8 warps (4 wm x 2 wn).
// grid(3, 128): o fastest -> 3 CTAs with same m run together (X L2 reuse).
// fp16 single-term: Y = X16 @ W16.  1 MMA per slice.
// ---------------------------------------------------------------------------
#define GS 40   // smem k-stride (halves): 80B rows, 16B aligned, LDSM-conflict-free
#define GEMM_SMEM (2 * 128 * GS * 2)

__global__ __launch_bounds__(256) void qkv_mma(const float* __restrict__ X)
{
    extern __shared__ __half smg[];
    __half* Xs = smg;                 // [128][GS]
    __half* Ws = Xs + 128 * GS;       // [128 n][GS]
    const u32 Xs_b = smem_u32(Xs);
    const u32 Ws_b = smem_u32(Ws);

    const int t    = threadIdx.x;
    const int lane = t & 31;
    const int wrp  = t >> 5;
    const int wm   = wrp >> 1;
    const int wn   = wrp & 1;
    const int g    = lane >> 2;
    const int qd   = (lane & 3) << 1;
    const int j    = lane >> 3;
    const int lr   = lane & 7;
    const int o    = blockIdx.x;
    const size_t m0 = (size_t)blockIdx.y * 128;

    u32 ga_off[2];
    #pragma unroll
    for (int mf = 0; mf < 2; mf++)
        ga_off[mf] = (wm * 32 + mf * 16 + ((j & 1) << 3) + lr) * 80 + ((j >> 1) << 4);
    const u32 gb_off = (wn * 64 + ((j >> 1) << 3) + lr) * 80 + ((j & 1) << 4);

    const __half* Wg = gW[o];

    float acc[2][8][4];
    #pragma unroll
    for (int mf = 0; mf < 2; mf++)
        #pragma unroll
        for (int nf = 0; nf < 8; nf++)
            #pragma unroll
            for (int e = 0; e < 4; e++) acc[mf][nf][e] = 0.f;

    float4 xv[4];
    uint4  wv[2];
    const int xr  = t >> 3;
    const int xc  = (t & 7) << 2;
    const int wn_ = t >> 2;
    const int wc  = (t & 3) << 3;

    #pragma unroll
    for (int i = 0; i < 4; i++)
        xv[i] = *reinterpret_cast<const float4*>(X + (m0 + xr + i * 32) * CIN + xc);
    #pragma unroll
    for (int i = 0; i < 2; i++)
        wv[i] = *reinterpret_cast<const uint4*>(&Wg[(wn_ + i * 64) * CIN + wc]);

    for (int it = 0; it < 32; it++) {
        __syncthreads();
        #pragma unroll
        for (int i = 0; i < 4; i++) {
            const int r = xr + i * 32;
            *reinterpret_cast<u32*>(&Xs[r * GS + xc])     = pack_half2(xv[i].x, xv[i].y);
            *reinterpret_cast<u32*>(&Xs[r * GS + xc + 2]) = pack_half2(xv[i].z, xv[i].w);
        }
        #pragma unroll
        for (int i = 0; i < 2; i++)
            *reinterpret_cast<uint4*>(&Ws[(wn_ + i * 64) * GS + wc]) = wv[i];
        __syncthreads();

        if (it < 31) {
            const int k1 = (it + 1) * 32;
            #pragma unroll
            for (int i = 0; i < 4; i++)
                xv[i] = *reinterpret_cast<const float4*>(X + (m0 + xr + i * 32) * CIN + k1 + xc);
            #pragma unroll
            for (int i = 0; i < 2; i++)
                wv[i] = *reinterpret_cast<const uint4*>(&Wg[(wn_ + i * 64) * CIN + k1 + wc]);
        }

        #pragma unroll
        for (int ks = 0; ks < 2; ks++) {
            u32 ah[2][4];
            #pragma unroll
            for (int mf = 0; mf < 2; mf++)
                ldsm4(Xs_b + ga_off[mf] + ks * 32, ah[mf][0], ah[mf][1], ah[mf][2], ah[mf][3]);
            #pragma unroll
            for (int nf2 = 0; nf2 < 4; nf2++) {
                u32 b0, b1, b2, b3;
                ldsm4(Ws_b + gb_off + nf2 * (16 * 80) + ks * 32, b0, b1, b2, b3);
                #pragma unroll
                for (int mf = 0; mf < 2; mf++) {
                    mma_f16(acc[mf][2 * nf2],     ah[mf], b0, b1);
                    mma_f16(acc[mf][2 * nf2 + 1], ah[mf], b2, b3);
                }
            }
        }
    }

    // Epilogue: scale Q by 1/sqrt(1024), round to fp16 globals
    const float scale = (o == 0) ? 0.03125f : 1.0f;
    __half* G = (o == 0) ? gQ : (o == 1 ? gK : gV);
    #pragma unroll
    for (int mf = 0; mf < 2; mf++) {
        const size_t r = m0 + wm * 32 + mf * 16 + g;
        #pragma unroll
        for (int nf = 0; nf < 8; nf++) {
            const int col = wn * 64 + nf * 8 + qd;
            *reinterpret_cast<u32*>(&G[r * HD + col]) =
                pack_half2(acc[mf][nf][0] * scale, acc[mf][nf][1] * scale);
            *reinterpret_cast<u32*>(&G[(r + 8) * HD + col]) =
                pack_half2(acc[mf][nf][2] * scale, acc[mf][nf][3] * scale);
        }
    }
}

// ---------------------------------------------------------------------------
// Kernel C: causal flash attention, fp16, cross-tile pipelined, PAIRED grid.
// grid(16, 8): CTA x processes q-tiles {x, 31-x} sequentially -> every CTA
// does exactly 33 tile-iters (perfect causal load balance, 128 CTAs = 1/SM).
// K double-buffered; V single-buffered issued at end of prior iter.
// ---------------------------------------------------------------------------
#define AST 136                      // smem row stride in halves (272 B)
#define TILE_B (64 * AST * 2)        // one 64x128 fp16 tile: 17408 B
#define ATTN_SMEM (3 * TILE_B)       // K0 K1 V = 52224 B

__device__ __forceinline__ void cp_tile64(u32 dst, const __half* src, int t)
{
    #pragma unroll
    for (int i = 0; i < 8; i++) {
        const int c   = t + i * 128;
        const int row = c >> 4;
        const int col = c & 15;
        CP16(dst + row * 272 + col * 16, src + row * 128 + col * 8);
    }
}

__global__ __launch_bounds__(128) void attn_kernel(float* __restrict__ out)
{
    extern __shared__ __half sma[];
    const u32 base = smem_u32(sma);
    const u32 K_s0 = base;
    const u32 K_s1 = base + TILE_B;
    const u32 V_b  = base + 2 * TILE_B;

    const int t    = threadIdx.x;
    const int lane = t & 31;
    const int w    = t >> 5;
    const int g    = lane >> 2;
    const int qd   = (lane & 3) << 1;
    const int j    = lane >> 3;
    const int lr   = lane & 7;
    const int b    = blockIdx.y;

    // ldmatrix byte offsets (stride 272B)
    const u32 a_off  = (w * 16 + ((j & 1) << 3) + lr) * 272 + ((j >> 1) << 4);
    const u32 kb_off = (((j >> 1) << 3) + lr) * 272 + ((j & 1) << 4);
    const u32 vb_off = (((j & 1) << 3) + lr) * 272 + ((j >> 1) << 4);

    #pragma unroll 1
    for (int half = 0; half < 2; half++) {
        const int qt = (half == 0) ? (31 - (int)blockIdx.x) : (int)blockIdx.x;
        const int i0 = qt * 64;

        // ---- prologue: K(0)->s0, V(0)->V, Q staged through s1 ----
        cp_tile64(K_s0, gK + ((size_t)b * TT) * HD, t);
        cp_tile64(V_b,  gV + ((size_t)b * TT) * HD, t);
        cp_tile64(K_s1, gQ + ((size_t)b * TT + i0) * HD, t);
        CP_COMMIT();
        CP_WAIT(0);
        __syncthreads();

        u32 qh[8][4];
        #pragma unroll
        for (int ks = 0; ks < 8; ks++)
            ldsm4(K_s1 + a_off + ks * 32, qh[ks][0], qh[ks][1], qh[ks][2], qh[ks][3]);

        float O[16][4];
        #pragma unroll
        for (int nf = 0; nf < 16; nf++)
            #pragma unroll
            for (int e = 0; e < 4; e++) O[nf][e] = 0.f;
        float mrow[2] = {-1e30f, -1e30f};
        float lrow[2] = {0.f, 0.f};

        for (int jt = 0; jt <= qt; jt++) {
            const int stage = jt & 1;
            const u32 kh = stage ? K_s1 : K_s0;

            CP_WAIT(1);          // K(jt) complete (V(jt) may still be in flight)
            __syncthreads();

            if (jt < qt)
                cp_tile64(stage ? K_s0 : K_s1,
                          gK + ((size_t)b * TT + (jt + 1) * 64) * HD, t);
            CP_COMMIT();         // empty group on last iter keeps cadence uniform

            // ---- S = Q K^T ----
            float s[8][4];
            #pragma unroll
            for (int nf = 0; nf < 8; nf++)
                #pragma unroll
                for (int e = 0; e < 4; e++) s[nf][e] = 0.f;

            #pragma unroll
            for (int ks = 0; ks < 8; ks++) {
                #pragma unroll
                for (int nf2 = 0; nf2 < 4; nf2++) {
                    u32 b0, b1, b2, b3;
                    ldsm4(kh + kb_off + nf2 * (16 * 272) + ks * 32, b0, b1, b2, b3);
                    mma_f16(s[2 * nf2],     qh[ks], b0, b1);
                    mma_f16(s[2 * nf2 + 1], qh[ks], b2, b3);
                }
            }

            // ---- causal mask on diagonal tile ----
            if (jt == qt) {
                #pragma unroll
                for (int nf = 0; nf < 8; nf++) {
                    const int c0 = nf * 8 + qd;
                    const int r0 = w * 16 + g;
                    if (c0     > r0)     s[nf][0] = -1e30f;
                    if (c0 + 1 > r0)     s[nf][1] = -1e30f;
                    if (c0     > r0 + 8) s[nf][2] = -1e30f;
                    if (c0 + 1 > r0 + 8) s[nf][3] = -1e30f;
                }
            }

            // ---- online softmax ----
            float mx0 = -1e30f, mx1 = -1e30f;
            #pragma unroll
            for (int nf = 0; nf < 8; nf++) {
                mx0 = fmaxf(mx0, fmaxf(s[nf][0], s[nf][1]));
                mx1 = fmaxf(mx1, fmaxf(s[nf][2], s[nf][3]));
            }
            mx0 = fmaxf(mx0, __shfl_xor_sync(0xffffffffu, mx0, 1));
            mx0 = fmaxf(mx0, __shfl_xor_sync(0xffffffffu, mx0, 2));
            mx1 = fmaxf(mx1, __shfl_xor_sync(0xffffffffu, mx1, 1));
            mx1 = fmaxf(mx1, __shfl_xor_sync(0xffffffffu, mx1, 2));
            const float mn0 = fmaxf(mrow[0], mx0);
            const float mn1 = fmaxf(mrow[1], mx1);
            const float a0  = __expf(mrow[0] - mn0);
            const float a1  = __expf(mrow[1] - mn1);
            mrow[0] = mn0; mrow[1] = mn1;

            float sum0 = 0.f, sum1 = 0.f;
            #pragma unroll
            for (int nf = 0; nf < 8; nf++) {
                s[nf][0] = __expf(s[nf][0] - mn0);
                s[nf][1] = __expf(s[nf][1] - mn0);
                s[nf][2] = __expf(s[nf][2] - mn1);
                s[nf][3] = __expf(s[nf][3] - mn1);
                sum0 += s[nf][0] + s[nf][1];
                sum1 += s[nf][2] + s[nf][3];
            }
            sum0 += __shfl_xor_sync(0xffffffffu, sum0, 1);
            sum0 += __shfl_xor_sync(0xffffffffu, sum0, 2);
            sum1 += __shfl_xor_sync(0xffffffffu, sum1, 1);
            sum1 += __shfl_xor_sync(0xffffffffu, sum1, 2);
            lrow[0] = lrow[0] * a0 + sum0;
            lrow[1] = lrow[1] * a1 + sum1;

            #pragma unroll
            for (int nf = 0; nf < 16; nf++) {
                O[nf][0] *= a0; O[nf][1] *= a0;
                O[nf][2] *= a1; O[nf][3] *= a1;
            }

            CP_WAIT(1);          // V(jt) complete (K(jt+1) may still be in flight)
            __syncthreads();

            // ---- O += P V : P rounded to fp16, V frags via ldmatrix.trans ----
            #pragma unroll
            for (int ks = 0; ks < 4; ks++) {
                u32 ph[4];
                ph[0] = pack_half2(s[2 * ks][0],     s[2 * ks][1]);
                ph[1] = pack_half2(s[2 * ks][2],     s[2 * ks][3]);
                ph[2] = pack_half2(s[2 * ks + 1][0], s[2 * ks + 1][1]);
                ph[3] = pack_half2(s[2 * ks + 1][2], s[2 * ks + 1][3]);
                #pragma unroll
                for (int nf2 = 0; nf2 < 8; nf2++) {
                    u32 b0, b1, b2, b3;
                    ldsm4t(V_b + vb_off + ks * (16 * 272) + nf2 * 32, b0, b1, b2, b3);
                    mma_f16(O[2 * nf2],     ph, b0, b1);
                    mma_f16(O[2 * nf2 + 1], ph, b2, b3);
                }
            }

            __syncthreads();     // all warps done reading V(jt) before overwrite
            if (jt < qt)
                cp_tile64(V_b, gV + ((size_t)b * TT + (jt + 1) * 64) * HD, t);
            CP_COMMIT();
        }

        // ---- epilogue: normalize + store fp32 ----
        const float inv0 = 1.0f / lrow[0];
        const float inv1 = 1.0f / lrow[1];
        const size_t r0 = (size_t)b * TT + i0 + w * 16 + g;
        #pragma unroll
        for (int nf = 0; nf < 16; nf++) {
            const int col = nf * 8 + qd;
            float2 v0 = make_float2(O[nf][0] * inv0, O[nf][1] * inv0);
            float2 v1 = make_float2(O[nf][2] * inv1, O[nf][3] * inv1);
            *reinterpret_cast<float2*>(out + r0 * HD + col)       = v0;
            *reinterpret_cast<float2*>(out + (r0 + 8) * HD + col) = v1;
        }

        CP_WAIT(0);              // drain outstanding empty groups before re-staging
        __syncthreads();
    }
}

// ---------------------------------------------------------------------------
extern "C" void kernel_launch(void* const* d_in, const int* in_sizes, int n_in,
                              void* d_out, int out_size)
{
    const float* X  = (const float*)d_in[0];   // [8,2048,1024]
    const float* Wq = (const float*)d_in[1];   // [1024,128]
    const float* Wk = (const float*)d_in[2];
    const float* Wv = (const float*)d_in[3];
    float* out = (float*)d_out;                // [8,2048,128]
    (void)in_sizes; (void)n_in; (void)out_size;

    cudaFuncSetAttribute(qkv_mma,
        cudaFuncAttributeMaxDynamicSharedMemorySize, GEMM_SMEM);
    cudaFuncSetAttribute(attn_kernel,
        cudaFuncAttributeMaxDynamicSharedMemorySize, ATTN_SMEM);

    convert_w<<<dim3(HD / 32, CIN / 32, 3), dim3(32, 8)>>>(Wq, Wk, Wv);
    qkv_mma<<<dim3(3, BT / 128), 256, GEMM_SMEM>>>(X);
    attn_kernel<<<dim3(16, BB), 128, ATTN_SMEM>>>(out);
}